// round 10
// baseline (speedup 1.0000x reference)
#include <cuda_runtime.h>
#include <mma.h>
#include <cstdint>

using namespace nvcuda;

#define Bn   16
#define Cn   256
#define Tn   1024
#define KEYn 256
#define INV_SQRT_K 0.0625f

// ---------------- scratch (device globals; no allocation allowed) ----------
__device__ float g_q[Bn * KEYn * Tn];            // channel-major [B,KEY,T]
__device__ float g_k[Bn * KEYn * Tn];            // channel-major [B,KEY,T]
__device__ float g_v[Bn * Tn * Cn];              // token-major   [B,T,C]
__device__ float g_attn[(size_t)Bn * Tn * Tn];   // exp(scores); upper tiles unused
__device__ float g_colpart[(size_t)16 * Bn * Tn];
__device__ float g_invcol[Bn * Tn];
__device__ float g_rowsum[Bn * Tn];
__device__ float g_wx[Bn * Tn];
__device__ float g_oa[Bn * Cn * Tn];
__device__ float g_h1[Bn * Cn * Tn];
__device__ float g_ws1[3 * Cn * Cn];             // weight-normed, split [r][c][o]
__device__ float g_ws2[3 * Cn * Cn];

// ---------------- weight norm -> split per-tap transposed layout -----------
__global__ __launch_bounds__(256) void wnorm_kernel(const float* __restrict__ v,
                                                    const float* __restrict__ g,
                                                    int which) {
    float* w = which ? g_ws2 : g_ws1;
    int o = blockIdx.x;
    int tid = threadIdx.x;
    __shared__ float red[256];
    float s = 0.f;
    for (int i = tid; i < Cn * 3; i += 256) {
        float t = v[o * Cn * 3 + i];
        s += t * t;
    }
    red[tid] = s;
    __syncthreads();
    for (int st = 128; st > 0; st >>= 1) {
        if (tid < st) red[tid] += red[tid + st];
        __syncthreads();
    }
    float scale = g[o] * rsqrtf(red[0]);
    for (int i = tid; i < Cn * 3; i += 256) {
        int c = i / 3, r = i - c * 3;
        w[(r * Cn + c) * Cn + o] = v[o * Cn * 3 + i] * scale;
    }
}

// helper: convert fragment floats to tf32 (RNE; also caps register liveness)
template <typename FragT>
__device__ __forceinline__ void to_tf32(FragT& f) {
#pragma unroll
    for (int i = 0; i < f.num_elements; i++) f.x[i] = wmma::__float_to_tf32(f.x[i]);
}

// ------- fused q/k/v projection (tf32 wmma, K-step 32) ---------------------
// blockIdx.y: 0-3 -> q, 4-7 -> k, 8-11 -> v.  out[n,t] = sum_c W[c,n]x[b,c,t]
__global__ __launch_bounds__(256) void gemm_qkv_wmma(
        const float* __restrict__ x,
        const float* __restrict__ Wq, const float* __restrict__ bq,
        const float* __restrict__ Wk, const float* __restrict__ bk,
        const float* __restrict__ Wv, const float* __restrict__ bv) {
    int b = blockIdx.z;
    int t0 = blockIdx.x * 64;
    int by = blockIdx.y;
    int which = by >> 2;               // 0=q 1=k 2=v
    int n0 = (by & 3) * 64;
    const float* W = (which == 0) ? Wq : (which == 1) ? Wk : Wv;
    const float* bias = (which == 0) ? bq : (which == 1) ? bk : bv;
    int tid = threadIdx.x;
    __shared__ union {
        struct { float W[32][72]; float X[32][72]; } mi;
        float S[64][72];
    } sm;
    int wid = tid >> 5;
    int m_off = (wid & 3) * 16;        // n
    int n_base = (wid >> 2) * 32;      // t
    wmma::fragment<wmma::accumulator, 16, 16, 8, float> acc[2];
    wmma::fill_fragment(acc[0], 0.f);
    wmma::fill_fragment(acc[1], 0.f);
    const float* xb = x + (size_t)b * Cn * Tn;
    int lr = tid >> 4, lc = (tid & 15) * 4;
    for (int c0 = 0; c0 < Cn; c0 += 32) {
        *(float4*)&sm.mi.W[lr][lc]      = *(const float4*)&W[(c0 + lr) * 256 + n0 + lc];
        *(float4*)&sm.mi.W[lr + 16][lc] = *(const float4*)&W[(c0 + lr + 16) * 256 + n0 + lc];
        *(float4*)&sm.mi.X[lr][lc]      = *(const float4*)&xb[(size_t)(c0 + lr) * Tn + t0 + lc];
        *(float4*)&sm.mi.X[lr + 16][lc] = *(const float4*)&xb[(size_t)(c0 + lr + 16) * Tn + t0 + lc];
        __syncthreads();
#pragma unroll
        for (int ks = 0; ks < 32; ks += 8) {
            wmma::fragment<wmma::matrix_a, 16, 16, 8, wmma::precision::tf32, wmma::col_major> a;
            wmma::load_matrix_sync(a, &sm.mi.W[ks][m_off], 72);
            to_tf32(a);
#pragma unroll
            for (int nf = 0; nf < 2; nf++) {
                wmma::fragment<wmma::matrix_b, 16, 16, 8, wmma::precision::tf32, wmma::row_major> bf;
                wmma::load_matrix_sync(bf, &sm.mi.X[ks][n_base + nf * 16], 72);
                to_tf32(bf);
                wmma::mma_sync(acc[nf], a, bf, acc[nf]);
            }
        }
        __syncthreads();
    }
    wmma::store_matrix_sync(&sm.S[m_off][n_base], acc[0], 72, wmma::mem_row_major);
    wmma::store_matrix_sync(&sm.S[m_off][n_base + 16], acc[1], 72, wmma::mem_row_major);
    __syncthreads();
    if (which < 2) {   // q/k: channel-major [n][t]
        float* out = (which == 0) ? g_q : g_k;
        int row = tid >> 2, colb = (tid & 3) * 16;
        int n = n0 + row;
        float bo = bias[n];
        float* orow = &out[((size_t)b * KEYn + n) * Tn + t0 + colb];
#pragma unroll
        for (int q = 0; q < 4; q++) {
            float4 res;
            res.x = sm.S[row][colb + q * 4 + 0] + bo;
            res.y = sm.S[row][colb + q * 4 + 1] + bo;
            res.z = sm.S[row][colb + q * 4 + 2] + bo;
            res.w = sm.S[row][colb + q * 4 + 3] + bo;
            *(float4*)&orow[q * 4] = res;
        }
    } else {           // v: token-major [t][c], transposed write via smem
        int col = tid >> 2;            // t index 0..63
        int rowb = (tid & 3) * 16;     // n chunk
#pragma unroll
        for (int q = 0; q < 4; q++) {
            float4 res;
            res.x = sm.S[rowb + q * 4 + 0][col] + bias[n0 + rowb + q * 4 + 0];
            res.y = sm.S[rowb + q * 4 + 1][col] + bias[n0 + rowb + q * 4 + 1];
            res.z = sm.S[rowb + q * 4 + 2][col] + bias[n0 + rowb + q * 4 + 2];
            res.w = sm.S[rowb + q * 4 + 3][col] + bias[n0 + rowb + q * 4 + 3];
            *(float4*)&g_v[((size_t)b * Tn + t0 + col) * Cn + n0 + rowb + q * 4] = res;
        }
    }
}

// ------- scores (tf32 wmma, triangular grid, K-step 32) --------------------
__global__ __launch_bounds__(256) void gemm_scores() {
    int b = blockIdx.z;
    // decode linear lower-triangle index -> (it, jt), it <= jt
    int idx = blockIdx.x;
    int jt = (int)((sqrtf(8.f * idx + 1.f) - 1.f) * 0.5f);
    while ((jt + 1) * (jt + 2) / 2 <= idx) jt++;
    while (jt * (jt + 1) / 2 > idx) jt--;
    int it = idx - jt * (jt + 1) / 2;
    int i0 = it * 64, j0 = jt * 64;
    int tid = threadIdx.x;
    float* S = g_attn + (size_t)b * Tn * Tn;
    float* cpart = g_colpart + (size_t)jt * Bn * Tn + b * Tn + i0;
    int c = tid & 63, rb = tid >> 6;
    __shared__ union {
        struct { float Q[32][72]; float K[32][72]; } mi;
        struct { float S[64][72]; float cred[4][64]; } ep;
    } sm;
    int wid = tid >> 5;
    int m_off = (wid & 3) * 16;
    int n_base = (wid >> 2) * 32;
    const float* qb = g_q + (size_t)b * KEYn * Tn;
    const float* kb = g_k + (size_t)b * KEYn * Tn;
    wmma::fragment<wmma::accumulator, 16, 16, 8, float> acc[2];
    wmma::fill_fragment(acc[0], 0.f);
    wmma::fill_fragment(acc[1], 0.f);
    int lr = tid >> 4, lc = (tid & 15) * 4;
    for (int kc = 0; kc < KEYn; kc += 32) {
        *(float4*)&sm.mi.Q[lr][lc]      = *(const float4*)&qb[(size_t)(kc + lr) * Tn + j0 + lc];
        *(float4*)&sm.mi.Q[lr + 16][lc] = *(const float4*)&qb[(size_t)(kc + lr + 16) * Tn + j0 + lc];
        *(float4*)&sm.mi.K[lr][lc]      = *(const float4*)&kb[(size_t)(kc + lr) * Tn + i0 + lc];
        *(float4*)&sm.mi.K[lr + 16][lc] = *(const float4*)&kb[(size_t)(kc + lr + 16) * Tn + i0 + lc];
        __syncthreads();
#pragma unroll
        for (int ks = 0; ks < 32; ks += 8) {
            wmma::fragment<wmma::matrix_a, 16, 16, 8, wmma::precision::tf32, wmma::col_major> a;
            wmma::load_matrix_sync(a, &sm.mi.Q[ks][m_off], 72);
            to_tf32(a);
#pragma unroll
            for (int nf = 0; nf < 2; nf++) {
                wmma::fragment<wmma::matrix_b, 16, 16, 8, wmma::precision::tf32, wmma::row_major> bf;
                wmma::load_matrix_sync(bf, &sm.mi.K[ks][n_base + nf * 16], 72);
                to_tf32(bf);
                wmma::mma_sync(acc[nf], a, bf, acc[nf]);
            }
        }
        __syncthreads();
    }
    wmma::store_matrix_sync(&sm.ep.S[m_off][n_base], acc[0], 72, wmma::mem_row_major);
    wmma::store_matrix_sync(&sm.ep.S[m_off][n_base + 16], acc[1], 72, wmma::mem_row_major);
    __syncthreads();
    float csum = 0.f;
#pragma unroll
    for (int rr = 0; rr < 16; rr++) {
        int row = rb * 16 + rr;
        int j = j0 + row, i = i0 + c;
        float e = (i <= j) ? __expf(sm.ep.S[row][c] * INV_SQRT_K) : 0.f;
        S[(size_t)j * Tn + i] = e;
        csum += e;
    }
    sm.ep.cred[rb][c] = csum;
    __syncthreads();
    if (tid < 64) {
        float s = sm.ep.cred[0][tid] + sm.ep.cred[1][tid]
                + sm.ep.cred[2][tid] + sm.ep.cred[3][tid];
        cpart[tid] = s;
    }
}

// ------- invcol[b,i] = 1 / sum_{p >= i_tile} colpart[p][b,i] ---------------
__global__ __launch_bounds__(256) void invcol_kernel() {
    int idx = blockIdx.x * 256 + threadIdx.x;
    int i = idx & (Tn - 1);
    int p0 = i >> 6;
    float s = 0.f;
    for (int p = p0; p < 16; p++) s += g_colpart[(size_t)p * Bn * Tn + idx];
    g_invcol[idx] = 1.f / s;
}

// ------- rowsum[b,j] = sum_{i<=j} e[b,j,i] * invcol[b,i] -------------------
__global__ __launch_bounds__(256) void row_sum() {
    int b = blockIdx.y;
    int j = blockIdx.x * 8 + (threadIdx.x >> 5);
    int lane = threadIdx.x & 31;
    const float* row = g_attn + (size_t)b * Tn * Tn + (size_t)j * Tn;
    const float* inv = g_invcol + b * Tn;
    float s = 0.f;
    for (int i = lane; i <= j; i += 32) s += row[i] * inv[i];
#pragma unroll
    for (int o = 16; o > 0; o >>= 1) s += __shfl_xor_sync(0xffffffffu, s, o);
    if (lane == 0) g_rowsum[b * Tn + j] = s;
}

// ------- weight_x[b,:] = softmax_j(rowsum[b,:]) ----------------------------
__global__ __launch_bounds__(256) void wx_softmax() {
    int b = blockIdx.x;
    int tid = threadIdx.x;
    __shared__ float red[256];
    const float* r = g_rowsum + b * Tn;
    float m = -1e30f;
    for (int j = tid; j < Tn; j += 256) m = fmaxf(m, r[j]);
    red[tid] = m;
    __syncthreads();
    for (int st = 128; st > 0; st >>= 1) {
        if (tid < st) red[tid] = fmaxf(red[tid], red[tid + st]);
        __syncthreads();
    }
    m = red[0];
    __syncthreads();
    float sum = 0.f;
    for (int j = tid; j < Tn; j += 256) sum += __expf(r[j] - m);
    red[tid] = sum;
    __syncthreads();
    for (int st = 128; st > 0; st >>= 1) {
        if (tid < st) red[tid] += red[tid + st];
        __syncthreads();
    }
    float inv = 1.f / red[0];
    for (int j = tid; j < Tn; j += 256)
        g_wx[b * Tn + j] = __expf(r[j] - m) * inv;
}

// ------- attn·V (tf32 wmma, K-step 32) -------------------------------------
__global__ __launch_bounds__(256) void gemm_av() {
    int b = blockIdx.z;
    int j0 = blockIdx.x * 64, c0 = blockIdx.y * 64;
    int tid = threadIdx.x;
    __shared__ float As[32][72];   // [i][c] scaled v
    __shared__ float Es[64][40];   // [j][i-chunk 32 + pad]
    const float* A = g_attn + (size_t)b * Tn * Tn;
    const float* V = g_v + (size_t)b * Tn * Cn;
    const float* inv = g_invcol + b * Tn;
    int wid = tid >> 5;
    int m_off = (wid & 3) * 16;          // c
    int n_base = (wid >> 2) * 32;        // j
    wmma::fragment<wmma::accumulator, 16, 16, 8, float> acc[2];
    wmma::fill_fragment(acc[0], 0.f);
    wmma::fill_fragment(acc[1], 0.f);
    int ar = tid >> 4, ac = (tid & 15) * 4;
    int er = tid >> 2, ec = (tid & 3) * 4;
    int kend = j0 + 64;
    for (int ii = 0; ii < kend; ii += 32) {
#pragma unroll
        for (int h = 0; h < 2; h++) {
            int irow = ii + ar + h * 16;
            float sc = inv[irow];
            float4 v4 = *(const float4*)&V[(size_t)irow * Cn + c0 + ac];
            *(float4*)&As[ar + h * 16][ac] =
                make_float4(v4.x * sc, v4.y * sc, v4.z * sc, v4.w * sc);
        }
        *(float4*)&Es[er][ec]      = *(const float4*)&A[(size_t)(j0 + er) * Tn + ii + ec];
        *(float4*)&Es[er][ec + 16] = *(const float4*)&A[(size_t)(j0 + er) * Tn + ii + ec + 16];
        __syncthreads();
#pragma unroll
        for (int ks = 0; ks < 32; ks += 8) {
            wmma::fragment<wmma::matrix_a, 16, 16, 8, wmma::precision::tf32, wmma::col_major> a;
            wmma::load_matrix_sync(a, &As[ks][m_off], 72);
            to_tf32(a);
#pragma unroll
            for (int nf = 0; nf < 2; nf++) {
                wmma::fragment<wmma::matrix_b, 16, 16, 8, wmma::precision::tf32, wmma::col_major> bf;
                wmma::load_matrix_sync(bf, &Es[n_base + nf * 16][ks], 40);
                to_tf32(bf);
                wmma::mma_sync(acc[nf], a, bf, acc[nf]);
            }
        }
        __syncthreads();
    }
    float* obase = &g_oa[((size_t)b * Cn + c0 + m_off) * Tn + j0];
    wmma::store_matrix_sync(obase + n_base, acc[0], Tn, wmma::mem_row_major);
    wmma::store_matrix_sync(obase + n_base + 16, acc[1], Tn, wmma::mem_row_major);
}

// ------- causal conv (tf32 wmma implicit GEMM, channel-step 32) ------------
template <int WHICH>
__global__ __launch_bounds__(256) void conv_kernel(const float* __restrict__ bias,
                                                   const float* __restrict__ x,
                                                   float* __restrict__ out_final) {
    const float* in = (WHICH == 1) ? g_oa : g_h1;
    const float* w  = (WHICH == 1) ? g_ws1 : g_ws2;
    float* out = (WHICH == 1) ? g_h1 : out_final;
    int b = blockIdx.z;
    int t0 = blockIdx.x * 64, o0 = blockIdx.y * 64;
    int tid = threadIdx.x;
    __shared__ union {
        struct { float A[3][32][72]; float I[3][32][72]; } mi;  // [r][c][o] / [r][c][t]
        float S[64][72];
    } sm;
    int wid = tid >> 5;
    int m_off = (wid & 3) * 16;       // o
    int n_base = (wid >> 2) * 32;     // t
    wmma::fragment<wmma::accumulator, 16, 16, 8, float> acc[2];
    wmma::fill_fragment(acc[0], 0.f);
    wmma::fill_fragment(acc[1], 0.f);
    const float* inb = in + (size_t)b * Cn * Tn;
    for (int cc0 = 0; cc0 < Cn; cc0 += 32) {
        // weights: 3 taps * 32 c * 64 o floats = 1536 float4
#pragma unroll
        for (int q = 0; q < 6; q++) {
            int lin = tid + q * 256;          // 0..1535
            int row = lin >> 4;               // 0..95
            int r = row >> 5, kk = row & 31;
            int col = (lin & 15) * 4;
            *(float4*)&sm.mi.A[r][kk][col] =
                *(const float4*)&w[((r * Cn) + cc0 + kk) * Cn + o0 + col];
        }
        // input windows: 3 taps * 32 c * 64 t scalars (tap shift breaks align)
#pragma unroll
        for (int q = 0; q < 24; q++) {
            int lin = tid + q * 256;          // 0..6143
            int r = lin >> 11;                // 2048 per tap
            int rem = lin & 2047;
            int kk = rem >> 6, col = rem & 63;
            int gt = t0 + col - 2 + r;
            sm.mi.I[r][kk][col] = (gt >= 0)
                ? inb[(size_t)(cc0 + kk) * Tn + gt] : 0.f;
        }
        __syncthreads();
#pragma unroll
        for (int r = 0; r < 3; r++) {
#pragma unroll
            for (int ks = 0; ks < 32; ks += 8) {
                wmma::fragment<wmma::matrix_a, 16, 16, 8, wmma::precision::tf32, wmma::col_major> a;
                wmma::load_matrix_sync(a, &sm.mi.A[r][ks][m_off], 72);
                to_tf32(a);
#pragma unroll
                for (int nf = 0; nf < 2; nf++) {
                    wmma::fragment<wmma::matrix_b, 16, 16, 8, wmma::precision::tf32, wmma::row_major> bf;
                    wmma::load_matrix_sync(bf, &sm.mi.I[r][ks][n_base + nf * 16], 72);
                    to_tf32(bf);
                    wmma::mma_sync(acc[nf], a, bf, acc[nf]);
                }
            }
        }
        __syncthreads();
    }
    wmma::store_matrix_sync(&sm.S[m_off][n_base], acc[0], 72, wmma::mem_row_major);
    wmma::store_matrix_sync(&sm.S[m_off][n_base + 16], acc[1], 72, wmma::mem_row_major);
    __syncthreads();
    int row = tid >> 2, colb = (tid & 3) * 16;
    int o = o0 + row;
    float bo = bias[o];
    if (WHICH == 2) {
        const float* xrow = &x[((size_t)b * Cn + o) * Tn + t0 + colb];
        const float* wxp = &g_wx[b * Tn + t0 + colb];
        float* orow = &out[((size_t)b * Cn + o) * Tn + t0 + colb];
#pragma unroll
        for (int q = 0; q < 4; q++) {
            float4 xv = *(const float4*)&xrow[q * 4];
            float4 wx4 = *(const float4*)&wxp[q * 4];
            float4 res;
            float h0 = fmaxf(sm.S[row][colb + q * 4 + 0] + bo, 0.f);
            float h1 = fmaxf(sm.S[row][colb + q * 4 + 1] + bo, 0.f);
            float h2 = fmaxf(sm.S[row][colb + q * 4 + 2] + bo, 0.f);
            float h3 = fmaxf(sm.S[row][colb + q * 4 + 3] + bo, 0.f);
            res.x = fmaxf(h0 + xv.x + wx4.x * xv.x, 0.f);
            res.y = fmaxf(h1 + xv.y + wx4.y * xv.y, 0.f);
            res.z = fmaxf(h2 + xv.z + wx4.z * xv.z, 0.f);
            res.w = fmaxf(h3 + xv.w + wx4.w * xv.w, 0.f);
            *(float4*)&orow[q * 4] = res;
        }
    } else {
        float* orow = &out[((size_t)b * Cn + o) * Tn + t0 + colb];
#pragma unroll
        for (int q = 0; q < 4; q++) {
            float4 res;
            res.x = fmaxf(sm.S[row][colb + q * 4 + 0] + bo, 0.f);
            res.y = fmaxf(sm.S[row][colb + q * 4 + 1] + bo, 0.f);
            res.z = fmaxf(sm.S[row][colb + q * 4 + 2] + bo, 0.f);
            res.w = fmaxf(sm.S[row][colb + q * 4 + 3] + bo, 0.f);
            *(float4*)&orow[q * 4] = res;
        }
    }
}

// ---------------------------------------------------------------------------
extern "C" void kernel_launch(void* const* d_in, const int* in_sizes, int n_in,
                              void* d_out, int out_size) {
    const float* x   = (const float*)d_in[0];
    const float* Wq  = (const float*)d_in[1];
    const float* bq  = (const float*)d_in[2];
    const float* Wk  = (const float*)d_in[3];
    const float* bk  = (const float*)d_in[4];
    const float* Wv  = (const float*)d_in[5];
    const float* bv  = (const float*)d_in[6];
    const float* c1v = (const float*)d_in[7];
    const float* c1g = (const float*)d_in[8];
    const float* c1b = (const float*)d_in[9];
    const float* c2v = (const float*)d_in[10];
    const float* c2g = (const float*)d_in[11];
    const float* c2b = (const float*)d_in[12];
    float* out = (float*)d_out;

    wnorm_kernel<<<Cn, 256>>>(c1v, c1g, 0);
    wnorm_kernel<<<Cn, 256>>>(c2v, c2g, 1);

    gemm_qkv_wmma<<<dim3(Tn / 64, 12, Bn), 256>>>(x, Wq, bq, Wk, bk, Wv, bv);

    gemm_scores<<<dim3(136, 1, Bn), 256>>>();   // triangular tile grid
    invcol_kernel<<<(Bn * Tn) / 256, 256>>>();
    row_sum<<<dim3(Tn / 8, Bn), 256>>>();
    wx_softmax<<<Bn, 256>>>();
    gemm_av<<<dim3(Tn / 64, Cn / 64, Bn), 256>>>();

    conv_kernel<1><<<dim3(Tn / 64, Cn / 64, Bn), 256>>>(c1b, x, nullptr);
    conv_kernel<2><<<dim3(Tn / 64, Cn / 64, Bn), 256>>>(c2b, x, out);
}

// round 11
// speedup vs baseline: 1.2875x; 1.2875x over previous
#include <cuda_runtime.h>
#include <cuda_bf16.h>
#include <mma.h>
#include <cstdint>

using namespace nvcuda;

#define Bn   16
#define Cn   256
#define Tn   1024
#define KEYn 256
#define INV_SQRT_K 0.0625f

// ---------------- scratch (device globals; no allocation allowed) ----------
__device__ float g_q[Bn * KEYn * Tn];            // channel-major [B,KEY,T]
__device__ float g_k[Bn * KEYn * Tn];            // channel-major [B,KEY,T]
__device__ float g_v[Bn * Tn * Cn];              // token-major   [B,T,C]
__device__ float g_attn[(size_t)Bn * Tn * Tn];   // exp(scores); upper tiles unused
__device__ float g_colpart[(size_t)16 * Bn * Tn];
__device__ float g_invcol[Bn * Tn];
__device__ float g_rowsum[Bn * Tn];
__device__ float g_wx[Bn * Tn];
__device__ float g_oa[Bn * Cn * Tn];
__device__ float g_h1[Bn * Cn * Tn];
__device__ __nv_bfloat16 g_ws1[3 * Cn * Cn];     // weight-normed bf16, [r][c][o]
__device__ __nv_bfloat16 g_ws2[3 * Cn * Cn];

// ---------------- weight norm -> split per-tap transposed bf16 layout ------
__global__ __launch_bounds__(256) void wnorm_kernel(const float* __restrict__ v,
                                                    const float* __restrict__ g,
                                                    int which) {
    __nv_bfloat16* w = which ? g_ws2 : g_ws1;
    int o = blockIdx.x;
    int tid = threadIdx.x;
    __shared__ float red[256];
    float s = 0.f;
    for (int i = tid; i < Cn * 3; i += 256) {
        float t = v[o * Cn * 3 + i];
        s += t * t;
    }
    red[tid] = s;
    __syncthreads();
    for (int st = 128; st > 0; st >>= 1) {
        if (tid < st) red[tid] += red[tid + st];
        __syncthreads();
    }
    float scale = g[o] * rsqrtf(red[0]);
    for (int i = tid; i < Cn * 3; i += 256) {
        int c = i / 3, r = i - c * 3;
        w[(r * Cn + c) * Cn + o] = __float2bfloat16(v[o * Cn * 3 + i] * scale);
    }
}

// helper: convert fragment floats to tf32 (RNE; also caps register liveness)
template <typename FragT>
__device__ __forceinline__ void to_tf32(FragT& f) {
#pragma unroll
    for (int i = 0; i < f.num_elements; i++) f.x[i] = wmma::__float_to_tf32(f.x[i]);
}

// ------- fused q/k/v projection (tf32 wmma, R9 form) -----------------------
__global__ __launch_bounds__(256) void gemm_qkv_wmma(
        const float* __restrict__ x,
        const float* __restrict__ Wq, const float* __restrict__ bq,
        const float* __restrict__ Wk, const float* __restrict__ bk,
        const float* __restrict__ Wv, const float* __restrict__ bv) {
    int b = blockIdx.z;
    int t0 = blockIdx.x * 64;
    int by = blockIdx.y;
    int which = by >> 2;               // 0=q 1=k 2=v
    int n0 = (by & 3) * 64;
    const float* W = (which == 0) ? Wq : (which == 1) ? Wk : Wv;
    const float* bias = (which == 0) ? bq : (which == 1) ? bk : bv;
    int tid = threadIdx.x;
    __shared__ float Ws[16][72];       // [c][n]
    __shared__ float Xs[16][72];       // [c][t]
    __shared__ float Ss[64][72];
    int wid = tid >> 5;
    int m_off = (wid & 3) * 16;        // n
    int n_base = (wid >> 2) * 32;      // t
    wmma::fragment<wmma::accumulator, 16, 16, 8, float> acc[2];
    wmma::fill_fragment(acc[0], 0.f);
    wmma::fill_fragment(acc[1], 0.f);
    const float* xb = x + (size_t)b * Cn * Tn;
    int lr = tid >> 4, lc = (tid & 15) * 4;
    for (int c0 = 0; c0 < Cn; c0 += 16) {
        *(float4*)&Ws[lr][lc] = *(const float4*)&W[(c0 + lr) * 256 + n0 + lc];
        *(float4*)&Xs[lr][lc] = *(const float4*)&xb[(size_t)(c0 + lr) * Tn + t0 + lc];
        __syncthreads();
#pragma unroll
        for (int ks = 0; ks < 16; ks += 8) {
            wmma::fragment<wmma::matrix_a, 16, 16, 8, wmma::precision::tf32, wmma::col_major> a;
            wmma::load_matrix_sync(a, &Ws[ks][m_off], 72);
#pragma unroll
            for (int nf = 0; nf < 2; nf++) {
                wmma::fragment<wmma::matrix_b, 16, 16, 8, wmma::precision::tf32, wmma::row_major> bf;
                wmma::load_matrix_sync(bf, &Xs[ks][n_base + nf * 16], 72);
                wmma::mma_sync(acc[nf], a, bf, acc[nf]);
            }
        }
        __syncthreads();
    }
    wmma::store_matrix_sync(&Ss[m_off][n_base], acc[0], 72, wmma::mem_row_major);
    wmma::store_matrix_sync(&Ss[m_off][n_base + 16], acc[1], 72, wmma::mem_row_major);
    __syncthreads();
    if (which < 2) {   // q/k: channel-major [n][t]
        float* out = (which == 0) ? g_q : g_k;
        int row = tid >> 2, colb = (tid & 3) * 16;
        int n = n0 + row;
        float bo = bias[n];
        float* orow = &out[((size_t)b * KEYn + n) * Tn + t0 + colb];
#pragma unroll
        for (int q = 0; q < 4; q++) {
            float4 res;
            res.x = Ss[row][colb + q * 4 + 0] + bo;
            res.y = Ss[row][colb + q * 4 + 1] + bo;
            res.z = Ss[row][colb + q * 4 + 2] + bo;
            res.w = Ss[row][colb + q * 4 + 3] + bo;
            *(float4*)&orow[q * 4] = res;
        }
    } else {           // v: token-major [t][c], transposed write via smem
        int col = tid >> 2;            // t index 0..63
        int rowb = (tid & 3) * 16;     // n chunk
#pragma unroll
        for (int q = 0; q < 4; q++) {
            float4 res;
            res.x = Ss[rowb + q * 4 + 0][col] + bias[n0 + rowb + q * 4 + 0];
            res.y = Ss[rowb + q * 4 + 1][col] + bias[n0 + rowb + q * 4 + 1];
            res.z = Ss[rowb + q * 4 + 2][col] + bias[n0 + rowb + q * 4 + 2];
            res.w = Ss[rowb + q * 4 + 3][col] + bias[n0 + rowb + q * 4 + 3];
            *(float4*)&g_v[((size_t)b * Tn + t0 + col) * Cn + n0 + rowb + q * 4] = res;
        }
    }
}

// ------- scores (tf32 wmma, triangular grid, K-step 32, union smem) --------
__global__ __launch_bounds__(256) void gemm_scores() {
    int b = blockIdx.z;
    int idx = blockIdx.x;
    int jt = (int)((sqrtf(8.f * idx + 1.f) - 1.f) * 0.5f);
    while ((jt + 1) * (jt + 2) / 2 <= idx) jt++;
    while (jt * (jt + 1) / 2 > idx) jt--;
    int it = idx - jt * (jt + 1) / 2;
    int i0 = it * 64, j0 = jt * 64;
    int tid = threadIdx.x;
    float* S = g_attn + (size_t)b * Tn * Tn;
    float* cpart = g_colpart + (size_t)jt * Bn * Tn + b * Tn + i0;
    int c = tid & 63, rb = tid >> 6;
    __shared__ union {
        struct { float Q[32][72]; float K[32][72]; } mi;
        struct { float S[64][72]; float cred[4][64]; } ep;
    } sm;
    int wid = tid >> 5;
    int m_off = (wid & 3) * 16;
    int n_base = (wid >> 2) * 32;
    const float* qb = g_q + (size_t)b * KEYn * Tn;
    const float* kb = g_k + (size_t)b * KEYn * Tn;
    wmma::fragment<wmma::accumulator, 16, 16, 8, float> acc[2];
    wmma::fill_fragment(acc[0], 0.f);
    wmma::fill_fragment(acc[1], 0.f);
    int lr = tid >> 4, lc = (tid & 15) * 4;
    for (int kc = 0; kc < KEYn; kc += 32) {
        *(float4*)&sm.mi.Q[lr][lc]      = *(const float4*)&qb[(size_t)(kc + lr) * Tn + j0 + lc];
        *(float4*)&sm.mi.Q[lr + 16][lc] = *(const float4*)&qb[(size_t)(kc + lr + 16) * Tn + j0 + lc];
        *(float4*)&sm.mi.K[lr][lc]      = *(const float4*)&kb[(size_t)(kc + lr) * Tn + i0 + lc];
        *(float4*)&sm.mi.K[lr + 16][lc] = *(const float4*)&kb[(size_t)(kc + lr + 16) * Tn + i0 + lc];
        __syncthreads();
#pragma unroll
        for (int ks = 0; ks < 32; ks += 8) {
            wmma::fragment<wmma::matrix_a, 16, 16, 8, wmma::precision::tf32, wmma::col_major> a;
            wmma::load_matrix_sync(a, &sm.mi.Q[ks][m_off], 72);
            to_tf32(a);
#pragma unroll
            for (int nf = 0; nf < 2; nf++) {
                wmma::fragment<wmma::matrix_b, 16, 16, 8, wmma::precision::tf32, wmma::row_major> bf;
                wmma::load_matrix_sync(bf, &sm.mi.K[ks][n_base + nf * 16], 72);
                to_tf32(bf);
                wmma::mma_sync(acc[nf], a, bf, acc[nf]);
            }
        }
        __syncthreads();
    }
    wmma::store_matrix_sync(&sm.ep.S[m_off][n_base], acc[0], 72, wmma::mem_row_major);
    wmma::store_matrix_sync(&sm.ep.S[m_off][n_base + 16], acc[1], 72, wmma::mem_row_major);
    __syncthreads();
    float csum = 0.f;
#pragma unroll
    for (int rr = 0; rr < 16; rr++) {
        int row = rb * 16 + rr;
        int j = j0 + row, i = i0 + c;
        float e = (i <= j) ? __expf(sm.ep.S[row][c] * INV_SQRT_K) : 0.f;
        S[(size_t)j * Tn + i] = e;
        csum += e;
    }
    sm.ep.cred[rb][c] = csum;
    __syncthreads();
    if (tid < 64) {
        float s = sm.ep.cred[0][tid] + sm.ep.cred[1][tid]
                + sm.ep.cred[2][tid] + sm.ep.cred[3][tid];
        cpart[tid] = s;
    }
}

// ------- invcol[b,i] = 1 / sum_{p >= i_tile} colpart[p][b,i] ---------------
__global__ __launch_bounds__(256) void invcol_kernel() {
    int idx = blockIdx.x * 256 + threadIdx.x;
    int i = idx & (Tn - 1);
    int p0 = i >> 6;
    float s = 0.f;
    for (int p = p0; p < 16; p++) s += g_colpart[(size_t)p * Bn * Tn + idx];
    g_invcol[idx] = 1.f / s;
}

// ------- rowsum[b,j] = sum_{i<=j} e[b,j,i] * invcol[b,i] -------------------
__global__ __launch_bounds__(256) void row_sum() {
    int b = blockIdx.y;
    int j = blockIdx.x * 8 + (threadIdx.x >> 5);
    int lane = threadIdx.x & 31;
    const float* row = g_attn + (size_t)b * Tn * Tn + (size_t)j * Tn;
    const float* inv = g_invcol + b * Tn;
    float s = 0.f;
    for (int i = lane; i <= j; i += 32) s += row[i] * inv[i];
#pragma unroll
    for (int o = 16; o > 0; o >>= 1) s += __shfl_xor_sync(0xffffffffu, s, o);
    if (lane == 0) g_rowsum[b * Tn + j] = s;
}

// ------- weight_x[b,:] = softmax_j(rowsum[b,:]) ----------------------------
__global__ __launch_bounds__(256) void wx_softmax() {
    int b = blockIdx.x;
    int tid = threadIdx.x;
    __shared__ float red[256];
    const float* r = g_rowsum + b * Tn;
    float m = -1e30f;
    for (int j = tid; j < Tn; j += 256) m = fmaxf(m, r[j]);
    red[tid] = m;
    __syncthreads();
    for (int st = 128; st > 0; st >>= 1) {
        if (tid < st) red[tid] = fmaxf(red[tid], red[tid + st]);
        __syncthreads();
    }
    m = red[0];
    __syncthreads();
    float sum = 0.f;
    for (int j = tid; j < Tn; j += 256) sum += __expf(r[j] - m);
    red[tid] = sum;
    __syncthreads();
    for (int st = 128; st > 0; st >>= 1) {
        if (tid < st) red[tid] += red[tid + st];
        __syncthreads();
    }
    float inv = 1.f / red[0];
    for (int j = tid; j < Tn; j += 256)
        g_wx[b * Tn + j] = __expf(r[j] - m) * inv;
}

// ------- attn·V (tf32 wmma, R9 form) ---------------------------------------
__global__ __launch_bounds__(256) void gemm_av() {
    int b = blockIdx.z;
    int j0 = blockIdx.x * 64, c0 = blockIdx.y * 64;
    int tid = threadIdx.x;
    __shared__ float As[16][72];   // [i][c] scaled v
    __shared__ float Es[64][24];   // [j][i-chunk]
    const float* A = g_attn + (size_t)b * Tn * Tn;
    const float* V = g_v + (size_t)b * Tn * Cn;
    const float* inv = g_invcol + b * Tn;
    int wid = tid >> 5;
    int m_off = (wid & 3) * 16;          // c
    int n_base = (wid >> 2) * 32;        // j
    wmma::fragment<wmma::accumulator, 16, 16, 8, float> acc[2];
    wmma::fill_fragment(acc[0], 0.f);
    wmma::fill_fragment(acc[1], 0.f);
    int ar = tid >> 4, ac = (tid & 15) * 4;
    int er = tid >> 2, ec = (tid & 3) * 4;
    int kend = j0 + 64;
    for (int ii = 0; ii < kend; ii += 16) {
        float sc = inv[ii + ar];
        float4 v4 = *(const float4*)&V[(size_t)(ii + ar) * Cn + c0 + ac];
        *(float4*)&As[ar][ac] = make_float4(v4.x * sc, v4.y * sc, v4.z * sc, v4.w * sc);
        *(float4*)&Es[er][ec] = *(const float4*)&A[(size_t)(j0 + er) * Tn + ii + ec];
        __syncthreads();
#pragma unroll
        for (int ks = 0; ks < 16; ks += 8) {
            wmma::fragment<wmma::matrix_a, 16, 16, 8, wmma::precision::tf32, wmma::col_major> a;
            wmma::load_matrix_sync(a, &As[ks][m_off], 72);
#pragma unroll
            for (int nf = 0; nf < 2; nf++) {
                wmma::fragment<wmma::matrix_b, 16, 16, 8, wmma::precision::tf32, wmma::col_major> bf;
                wmma::load_matrix_sync(bf, &Es[n_base + nf * 16][ks], 24);
                wmma::mma_sync(acc[nf], a, bf, acc[nf]);
            }
        }
        __syncthreads();
    }
    float* obase = &g_oa[((size_t)b * Cn + c0 + m_off) * Tn + j0];
    wmma::store_matrix_sync(obase + n_base, acc[0], Tn, wmma::mem_row_major);
    wmma::store_matrix_sync(obase + n_base + 16, acc[1], Tn, wmma::mem_row_major);
}

// ------- causal conv (bf16 wmma 16x16x16 implicit GEMM, KS=3) + fusion -----
template <int WHICH>
__global__ __launch_bounds__(256) void conv_kernel(const float* __restrict__ bias,
                                                   const float* __restrict__ x,
                                                   float* __restrict__ out_final) {
    const float* in = (WHICH == 1) ? g_oa : g_h1;
    const __nv_bfloat16* w = (WHICH == 1) ? g_ws1 : g_ws2;
    float* out = (WHICH == 1) ? g_h1 : out_final;
    int b = blockIdx.z;
    int t0 = blockIdx.x * 64, o0 = blockIdx.y * 64;
    int tid = threadIdx.x;
    __shared__ alignas(16) __nv_bfloat16 As[3][16][72];   // [r][c][o]
    __shared__ alignas(16) __nv_bfloat16 In3[3][16][72];  // [r][c][t per tap]
    __shared__ float Ss[64][72];
    int wid = tid >> 5;
    int m_off = (wid & 3) * 16;       // o
    int n_base = (wid >> 2) * 32;     // t
    wmma::fragment<wmma::accumulator, 16, 16, 16, float> acc[2];
    wmma::fill_fragment(acc[0], 0.f);
    wmma::fill_fragment(acc[1], 0.f);
    const float* inb = in + (size_t)b * Cn * Tn;
    for (int cc0 = 0; cc0 < Cn; cc0 += 16) {
        // weights: 3 taps * 16 c * 64 o bf16 = 768 float2 chunks (4 bf16 each)
#pragma unroll
        for (int q = 0; q < 3; q++) {
            int lin = tid + q * 256;          // 0..767
            int row = lin >> 4;               // 0..47
            int r = row >> 4, kk = row & 15;
            int col = (lin & 15) * 4;
            *(float2*)&As[r][kk][col] =
                *(const float2*)&w[((r * Cn) + cc0 + kk) * Cn + o0 + col];
        }
        // input windows: scalar fp32->bf16 converts (tap shift breaks align)
#pragma unroll
        for (int q = 0; q < 12; q++) {
            int lin = tid + q * 256;          // 0..3071
            int r = lin >> 10;
            int rem = lin & 1023;
            int kk = rem >> 6, col = rem & 63;
            int gt = t0 + col - 2 + r;
            In3[r][kk][col] = __float2bfloat16(
                (gt >= 0) ? inb[(size_t)(cc0 + kk) * Tn + gt] : 0.f);
        }
        __syncthreads();
#pragma unroll
        for (int r = 0; r < 3; r++) {
            wmma::fragment<wmma::matrix_a, 16, 16, 16, __nv_bfloat16, wmma::col_major> a;
            wmma::load_matrix_sync(a, &As[r][0][m_off], 72);
#pragma unroll
            for (int nf = 0; nf < 2; nf++) {
                wmma::fragment<wmma::matrix_b, 16, 16, 16, __nv_bfloat16, wmma::row_major> bf;
                wmma::load_matrix_sync(bf, &In3[r][0][n_base + nf * 16], 72);
                wmma::mma_sync(acc[nf], a, bf, acc[nf]);
            }
        }
        __syncthreads();
    }
    wmma::store_matrix_sync(&Ss[m_off][n_base], acc[0], 72, wmma::mem_row_major);
    wmma::store_matrix_sync(&Ss[m_off][n_base + 16], acc[1], 72, wmma::mem_row_major);
    __syncthreads();
    int row = tid >> 2, colb = (tid & 3) * 16;
    int o = o0 + row;
    float bo = bias[o];
    if (WHICH == 2) {
        const float* xrow = &x[((size_t)b * Cn + o) * Tn + t0 + colb];
        const float* wxp = &g_wx[b * Tn + t0 + colb];
        float* orow = &out[((size_t)b * Cn + o) * Tn + t0 + colb];
#pragma unroll
        for (int q = 0; q < 4; q++) {
            float4 xv = *(const float4*)&xrow[q * 4];
            float4 wx4 = *(const float4*)&wxp[q * 4];
            float4 res;
            float h0 = fmaxf(Ss[row][colb + q * 4 + 0] + bo, 0.f);
            float h1 = fmaxf(Ss[row][colb + q * 4 + 1] + bo, 0.f);
            float h2 = fmaxf(Ss[row][colb + q * 4 + 2] + bo, 0.f);
            float h3 = fmaxf(Ss[row][colb + q * 4 + 3] + bo, 0.f);
            res.x = fmaxf(h0 + xv.x + wx4.x * xv.x, 0.f);
            res.y = fmaxf(h1 + xv.y + wx4.y * xv.y, 0.f);
            res.z = fmaxf(h2 + xv.z + wx4.z * xv.z, 0.f);
            res.w = fmaxf(h3 + xv.w + wx4.w * xv.w, 0.f);
            *(float4*)&orow[q * 4] = res;
        }
    } else {
        float* orow = &out[((size_t)b * Cn + o) * Tn + t0 + colb];
#pragma unroll
        for (int q = 0; q < 4; q++) {
            float4 res;
            res.x = fmaxf(Ss[row][colb + q * 4 + 0] + bo, 0.f);
            res.y = fmaxf(Ss[row][colb + q * 4 + 1] + bo, 0.f);
            res.z = fmaxf(Ss[row][colb + q * 4 + 2] + bo, 0.f);
            res.w = fmaxf(Ss[row][colb + q * 4 + 3] + bo, 0.f);
            *(float4*)&orow[q * 4] = res;
        }
    }
}

// ---------------------------------------------------------------------------
extern "C" void kernel_launch(void* const* d_in, const int* in_sizes, int n_in,
                              void* d_out, int out_size) {
    const float* x   = (const float*)d_in[0];
    const float* Wq  = (const float*)d_in[1];
    const float* bq  = (const float*)d_in[2];
    const float* Wk  = (const float*)d_in[3];
    const float* bk  = (const float*)d_in[4];
    const float* Wv  = (const float*)d_in[5];
    const float* bv  = (const float*)d_in[6];
    const float* c1v = (const float*)d_in[7];
    const float* c1g = (const float*)d_in[8];
    const float* c1b = (const float*)d_in[9];
    const float* c2v = (const float*)d_in[10];
    const float* c2g = (const float*)d_in[11];
    const float* c2b = (const float*)d_in[12];
    float* out = (float*)d_out;

    wnorm_kernel<<<Cn, 256>>>(c1v, c1g, 0);
    wnorm_kernel<<<Cn, 256>>>(c2v, c2g, 1);

    gemm_qkv_wmma<<<dim3(Tn / 64, 12, Bn), 256>>>(x, Wq, bq, Wk, bk, Wv, bv);

    gemm_scores<<<dim3(136, 1, Bn), 256>>>();   // triangular tile grid
    invcol_kernel<<<(Bn * Tn) / 256, 256>>>();
    row_sum<<<dim3(Tn / 8, Bn), 256>>>();
    wx_softmax<<<Bn, 256>>>();
    gemm_av<<<dim3(Tn / 64, Cn / 64, Bn), 256>>>();

    conv_kernel<1><<<dim3(Tn / 64, Cn / 64, Bn), 256>>>(c1b, x, nullptr);
    conv_kernel<2><<<dim3(Tn / 64, Cn / 64, Bn), 256>>>(c2b, x, out);
}

// round 12
// speedup vs baseline: 1.4655x; 1.1382x over previous
#include <cuda_runtime.h>
#include <cuda_bf16.h>
#include <mma.h>
#include <cstdint>

using namespace nvcuda;

#define Bn   16
#define Cn   256
#define Tn   1024
#define KEYn 256
#define INV_SQRT_K 0.0625f

// ---------------- scratch (device globals; no allocation allowed) ----------
__device__ float g_q[Bn * KEYn * Tn];            // channel-major [B,KEY,T]
__device__ float g_k[Bn * KEYn * Tn];            // channel-major [B,KEY,T]
__device__ float g_v[Bn * Tn * Cn];              // token-major   [B,T,C]
__device__ __nv_bfloat16 g_attn[(size_t)Bn * Tn * Tn]; // exp(scores), bf16
__device__ float g_colpart[(size_t)16 * Bn * Tn];
__device__ float g_invcol[Bn * Tn];
__device__ float g_rowsum[Bn * Tn];
__device__ float g_wx[Bn * Tn];
__device__ float g_oa[Bn * Cn * Tn];
__device__ float g_h1[Bn * Cn * Tn];
__device__ __nv_bfloat16 g_ws1[3 * Cn * Cn];     // weight-normed bf16, [r][c][o]
__device__ __nv_bfloat16 g_ws2[3 * Cn * Cn];

// ---------------- weight norm -> split per-tap transposed bf16 layout ------
__global__ __launch_bounds__(256) void wnorm_kernel(const float* __restrict__ v,
                                                    const float* __restrict__ g,
                                                    int which) {
    __nv_bfloat16* w = which ? g_ws2 : g_ws1;
    int o = blockIdx.x;
    int tid = threadIdx.x;
    __shared__ float red[256];
    float s = 0.f;
    for (int i = tid; i < Cn * 3; i += 256) {
        float t = v[o * Cn * 3 + i];
        s += t * t;
    }
    red[tid] = s;
    __syncthreads();
    for (int st = 128; st > 0; st >>= 1) {
        if (tid < st) red[tid] += red[tid + st];
        __syncthreads();
    }
    float scale = g[o] * rsqrtf(red[0]);
    for (int i = tid; i < Cn * 3; i += 256) {
        int c = i / 3, r = i - c * 3;
        w[(r * Cn + c) * Cn + o] = __float2bfloat16(v[o * Cn * 3 + i] * scale);
    }
}

// helper: convert fragment floats to tf32 (RNE; also caps register liveness)
template <typename FragT>
__device__ __forceinline__ void to_tf32(FragT& f) {
#pragma unroll
    for (int i = 0; i < f.num_elements; i++) f.x[i] = wmma::__float_to_tf32(f.x[i]);
}

// ------- fused q/k/v projection (tf32 wmma, K-step 32, union smem) ---------
__global__ __launch_bounds__(256) void gemm_qkv_wmma(
        const float* __restrict__ x,
        const float* __restrict__ Wq, const float* __restrict__ bq,
        const float* __restrict__ Wk, const float* __restrict__ bk,
        const float* __restrict__ Wv, const float* __restrict__ bv) {
    int b = blockIdx.z;
    int t0 = blockIdx.x * 64;
    int by = blockIdx.y;
    int which = by >> 2;               // 0=q 1=k 2=v
    int n0 = (by & 3) * 64;
    const float* W = (which == 0) ? Wq : (which == 1) ? Wk : Wv;
    const float* bias = (which == 0) ? bq : (which == 1) ? bk : bv;
    int tid = threadIdx.x;
    __shared__ union {
        struct { float W[32][72]; float X[32][72]; } mi;
        float S[64][72];
    } sm;
    int wid = tid >> 5;
    int m_off = (wid & 3) * 16;        // n
    int n_base = (wid >> 2) * 32;      // t
    wmma::fragment<wmma::accumulator, 16, 16, 8, float> acc[2];
    wmma::fill_fragment(acc[0], 0.f);
    wmma::fill_fragment(acc[1], 0.f);
    const float* xb = x + (size_t)b * Cn * Tn;
    int lr = tid >> 4, lc = (tid & 15) * 4;
    for (int c0 = 0; c0 < Cn; c0 += 32) {
        *(float4*)&sm.mi.W[lr][lc]      = *(const float4*)&W[(c0 + lr) * 256 + n0 + lc];
        *(float4*)&sm.mi.W[lr + 16][lc] = *(const float4*)&W[(c0 + lr + 16) * 256 + n0 + lc];
        *(float4*)&sm.mi.X[lr][lc]      = *(const float4*)&xb[(size_t)(c0 + lr) * Tn + t0 + lc];
        *(float4*)&sm.mi.X[lr + 16][lc] = *(const float4*)&xb[(size_t)(c0 + lr + 16) * Tn + t0 + lc];
        __syncthreads();
#pragma unroll
        for (int ks = 0; ks < 32; ks += 8) {
            wmma::fragment<wmma::matrix_a, 16, 16, 8, wmma::precision::tf32, wmma::col_major> a;
            wmma::load_matrix_sync(a, &sm.mi.W[ks][m_off], 72);
#pragma unroll
            for (int nf = 0; nf < 2; nf++) {
                wmma::fragment<wmma::matrix_b, 16, 16, 8, wmma::precision::tf32, wmma::row_major> bf;
                wmma::load_matrix_sync(bf, &sm.mi.X[ks][n_base + nf * 16], 72);
                wmma::mma_sync(acc[nf], a, bf, acc[nf]);
            }
        }
        __syncthreads();
    }
    wmma::store_matrix_sync(&sm.S[m_off][n_base], acc[0], 72, wmma::mem_row_major);
    wmma::store_matrix_sync(&sm.S[m_off][n_base + 16], acc[1], 72, wmma::mem_row_major);
    __syncthreads();
    if (which < 2) {   // q/k: channel-major [n][t]
        float* out = (which == 0) ? g_q : g_k;
        int row = tid >> 2, colb = (tid & 3) * 16;
        int n = n0 + row;
        float bo = bias[n];
        float* orow = &out[((size_t)b * KEYn + n) * Tn + t0 + colb];
#pragma unroll
        for (int q = 0; q < 4; q++) {
            float4 res;
            res.x = sm.S[row][colb + q * 4 + 0] + bo;
            res.y = sm.S[row][colb + q * 4 + 1] + bo;
            res.z = sm.S[row][colb + q * 4 + 2] + bo;
            res.w = sm.S[row][colb + q * 4 + 3] + bo;
            *(float4*)&orow[q * 4] = res;
        }
    } else {           // v: token-major [t][c], transposed write via smem
        int col = tid >> 2;            // t index 0..63
        int rowb = (tid & 3) * 16;     // n chunk
#pragma unroll
        for (int q = 0; q < 4; q++) {
            float4 res;
            res.x = sm.S[rowb + q * 4 + 0][col] + bias[n0 + rowb + q * 4 + 0];
            res.y = sm.S[rowb + q * 4 + 1][col] + bias[n0 + rowb + q * 4 + 1];
            res.z = sm.S[rowb + q * 4 + 2][col] + bias[n0 + rowb + q * 4 + 2];
            res.w = sm.S[rowb + q * 4 + 3][col] + bias[n0 + rowb + q * 4 + 3];
            *(float4*)&g_v[((size_t)b * Tn + t0 + col) * Cn + n0 + rowb + q * 4] = res;
        }
    }
}

// ------- scores (tf32 wmma, triangular grid, K-step 32, bf16 output) -------
__global__ __launch_bounds__(256) void gemm_scores() {
    int b = blockIdx.z;
    int idx = blockIdx.x;
    int jt = (int)((sqrtf(8.f * idx + 1.f) - 1.f) * 0.5f);
    while ((jt + 1) * (jt + 2) / 2 <= idx) jt++;
    while (jt * (jt + 1) / 2 > idx) jt--;
    int it = idx - jt * (jt + 1) / 2;
    int i0 = it * 64, j0 = jt * 64;
    int tid = threadIdx.x;
    __nv_bfloat16* S = g_attn + (size_t)b * Tn * Tn;
    float* cpart = g_colpart + (size_t)jt * Bn * Tn + b * Tn + i0;
    int c = tid & 63, rb = tid >> 6;
    __shared__ union {
        struct { float Q[32][72]; float K[32][72]; } mi;
        struct { float S[64][72]; float cred[4][64]; } ep;
    } sm;
    int wid = tid >> 5;
    int m_off = (wid & 3) * 16;
    int n_base = (wid >> 2) * 32;
    const float* qb = g_q + (size_t)b * KEYn * Tn;
    const float* kb = g_k + (size_t)b * KEYn * Tn;
    wmma::fragment<wmma::accumulator, 16, 16, 8, float> acc[2];
    wmma::fill_fragment(acc[0], 0.f);
    wmma::fill_fragment(acc[1], 0.f);
    int lr = tid >> 4, lc = (tid & 15) * 4;
    for (int kc = 0; kc < KEYn; kc += 32) {
        *(float4*)&sm.mi.Q[lr][lc]      = *(const float4*)&qb[(size_t)(kc + lr) * Tn + j0 + lc];
        *(float4*)&sm.mi.Q[lr + 16][lc] = *(const float4*)&qb[(size_t)(kc + lr + 16) * Tn + j0 + lc];
        *(float4*)&sm.mi.K[lr][lc]      = *(const float4*)&kb[(size_t)(kc + lr) * Tn + i0 + lc];
        *(float4*)&sm.mi.K[lr + 16][lc] = *(const float4*)&kb[(size_t)(kc + lr + 16) * Tn + i0 + lc];
        __syncthreads();
#pragma unroll
        for (int ks = 0; ks < 32; ks += 8) {
            wmma::fragment<wmma::matrix_a, 16, 16, 8, wmma::precision::tf32, wmma::col_major> a;
            wmma::load_matrix_sync(a, &sm.mi.Q[ks][m_off], 72);
            to_tf32(a);
#pragma unroll
            for (int nf = 0; nf < 2; nf++) {
                wmma::fragment<wmma::matrix_b, 16, 16, 8, wmma::precision::tf32, wmma::row_major> bf;
                wmma::load_matrix_sync(bf, &sm.mi.K[ks][n_base + nf * 16], 72);
                to_tf32(bf);
                wmma::mma_sync(acc[nf], a, bf, acc[nf]);
            }
        }
        __syncthreads();
    }
    wmma::store_matrix_sync(&sm.ep.S[m_off][n_base], acc[0], 72, wmma::mem_row_major);
    wmma::store_matrix_sync(&sm.ep.S[m_off][n_base + 16], acc[1], 72, wmma::mem_row_major);
    __syncthreads();
    float csum = 0.f;
#pragma unroll
    for (int rr = 0; rr < 16; rr++) {
        int row = rb * 16 + rr;
        int j = j0 + row, i = i0 + c;
        float e = (i <= j) ? __expf(sm.ep.S[row][c] * INV_SQRT_K) : 0.f;
        S[(size_t)j * Tn + i] = __float2bfloat16(e);
        csum += e;
    }
    sm.ep.cred[rb][c] = csum;
    __syncthreads();
    if (tid < 64) {
        float s = sm.ep.cred[0][tid] + sm.ep.cred[1][tid]
                + sm.ep.cred[2][tid] + sm.ep.cred[3][tid];
        cpart[tid] = s;
    }
}

// ------- invcol[b,i] = 1 / sum_{p >= i_tile} colpart[p][b,i] ---------------
__global__ __launch_bounds__(256) void invcol_kernel() {
    int idx = blockIdx.x * 256 + threadIdx.x;
    int i = idx & (Tn - 1);
    int p0 = i >> 6;
    float s = 0.f;
    for (int p = p0; p < 16; p++) s += g_colpart[(size_t)p * Bn * Tn + idx];
    g_invcol[idx] = 1.f / s;
}

// ------- rowsum[b,j] = sum_{i<=j} e[b,j,i] * invcol[b,i] -------------------
__global__ __launch_bounds__(256) void row_sum() {
    int b = blockIdx.y;
    int j = blockIdx.x * 8 + (threadIdx.x >> 5);
    int lane = threadIdx.x & 31;
    const __nv_bfloat16* row = g_attn + (size_t)b * Tn * Tn + (size_t)j * Tn;
    const float* inv = g_invcol + b * Tn;
    float s = 0.f;
    for (int i = lane; i <= j; i += 32) s += __bfloat162float(row[i]) * inv[i];
#pragma unroll
    for (int o = 16; o > 0; o >>= 1) s += __shfl_xor_sync(0xffffffffu, s, o);
    if (lane == 0) g_rowsum[b * Tn + j] = s;
}

// ------- weight_x[b,:] = softmax_j(rowsum[b,:]) ----------------------------
__global__ __launch_bounds__(256) void wx_softmax() {
    int b = blockIdx.x;
    int tid = threadIdx.x;
    __shared__ float red[256];
    const float* r = g_rowsum + b * Tn;
    float m = -1e30f;
    for (int j = tid; j < Tn; j += 256) m = fmaxf(m, r[j]);
    red[tid] = m;
    __syncthreads();
    for (int st = 128; st > 0; st >>= 1) {
        if (tid < st) red[tid] = fmaxf(red[tid], red[tid + st]);
        __syncthreads();
    }
    m = red[0];
    __syncthreads();
    float sum = 0.f;
    for (int j = tid; j < Tn; j += 256) sum += __expf(r[j] - m);
    red[tid] = sum;
    __syncthreads();
    for (int st = 128; st > 0; st >>= 1) {
        if (tid < st) red[tid] += red[tid + st];
        __syncthreads();
    }
    float inv = 1.f / red[0];
    for (int j = tid; j < Tn; j += 256)
        g_wx[b * Tn + j] = __expf(r[j] - m) * inv;
}

// ------- attn·V (bf16 wmma 16x16x16): oa = sum_i e[j,i]*invcol[i]*v[i,c] ---
__global__ __launch_bounds__(256) void gemm_av() {
    int b = blockIdx.z;
    int j0 = blockIdx.x * 64, c0 = blockIdx.y * 64;
    int tid = threadIdx.x;
    __shared__ alignas(16) __nv_bfloat16 As[16][72];   // [i][c] scaled v
    __shared__ alignas(16) __nv_bfloat16 Es[64][24];   // [j][i-chunk]
    const __nv_bfloat16* A = g_attn + (size_t)b * Tn * Tn;
    const float* V = g_v + (size_t)b * Tn * Cn;
    const float* inv = g_invcol + b * Tn;
    int wid = tid >> 5;
    int m_off = (wid & 3) * 16;          // c
    int n_base = (wid >> 2) * 32;        // j
    wmma::fragment<wmma::accumulator, 16, 16, 16, float> acc[2];
    wmma::fill_fragment(acc[0], 0.f);
    wmma::fill_fragment(acc[1], 0.f);
    int ar = tid >> 4, ac = (tid & 15) * 4;
    int er = tid >> 2, ec = (tid & 3) * 4;
    int kend = j0 + 64;
    for (int ii = 0; ii < kend; ii += 16) {
        float sc = inv[ii + ar];
        float4 v4 = *(const float4*)&V[(size_t)(ii + ar) * Cn + c0 + ac];
        *(__nv_bfloat162*)&As[ar][ac] =
            __floats2bfloat162_rn(v4.x * sc, v4.y * sc);
        *(__nv_bfloat162*)&As[ar][ac + 2] =
            __floats2bfloat162_rn(v4.z * sc, v4.w * sc);
        // 4 bf16 (8 bytes) direct copy from bf16 attn
        *(float2*)&Es[er][ec] = *(const float2*)&A[(size_t)(j0 + er) * Tn + ii + ec];
        __syncthreads();
        wmma::fragment<wmma::matrix_a, 16, 16, 16, __nv_bfloat16, wmma::col_major> a;
        wmma::load_matrix_sync(a, &As[0][m_off], 72);
#pragma unroll
        for (int nf = 0; nf < 2; nf++) {
            wmma::fragment<wmma::matrix_b, 16, 16, 16, __nv_bfloat16, wmma::col_major> bf;
            wmma::load_matrix_sync(bf, &Es[n_base + nf * 16][0], 24);
            wmma::mma_sync(acc[nf], a, bf, acc[nf]);
        }
        __syncthreads();
    }
    float* obase = &g_oa[((size_t)b * Cn + c0 + m_off) * Tn + j0];
    wmma::store_matrix_sync(obase + n_base, acc[0], Tn, wmma::mem_row_major);
    wmma::store_matrix_sync(obase + n_base + 16, acc[1], Tn, wmma::mem_row_major);
}

// ------- causal conv (bf16 wmma 16x16x16 implicit GEMM, KS=3) + fusion -----
template <int WHICH>
__global__ __launch_bounds__(256) void conv_kernel(const float* __restrict__ bias,
                                                   const float* __restrict__ x,
                                                   float* __restrict__ out_final) {
    const float* in = (WHICH == 1) ? g_oa : g_h1;
    const __nv_bfloat16* w = (WHICH == 1) ? g_ws1 : g_ws2;
    float* out = (WHICH == 1) ? g_h1 : out_final;
    int b = blockIdx.z;
    int t0 = blockIdx.x * 64, o0 = blockIdx.y * 64;
    int tid = threadIdx.x;
    __shared__ alignas(16) __nv_bfloat16 As[3][16][72];   // [r][c][o]
    __shared__ alignas(16) __nv_bfloat16 In3[3][16][72];  // [r][c][t per tap]
    __shared__ float Ss[64][72];
    int wid = tid >> 5;
    int m_off = (wid & 3) * 16;       // o
    int n_base = (wid >> 2) * 32;     // t
    wmma::fragment<wmma::accumulator, 16, 16, 16, float> acc[2];
    wmma::fill_fragment(acc[0], 0.f);
    wmma::fill_fragment(acc[1], 0.f);
    const float* inb = in + (size_t)b * Cn * Tn;
    for (int cc0 = 0; cc0 < Cn; cc0 += 16) {
#pragma unroll
        for (int q = 0; q < 3; q++) {
            int lin = tid + q * 256;          // 0..767
            int row = lin >> 4;               // 0..47
            int r = row >> 4, kk = row & 15;
            int col = (lin & 15) * 4;
            *(float2*)&As[r][kk][col] =
                *(const float2*)&w[((r * Cn) + cc0 + kk) * Cn + o0 + col];
        }
#pragma unroll
        for (int q = 0; q < 12; q++) {
            int lin = tid + q * 256;          // 0..3071
            int r = lin >> 10;
            int rem = lin & 1023;
            int kk = rem >> 6, col = rem & 63;
            int gt = t0 + col - 2 + r;
            In3[r][kk][col] = __float2bfloat16(
                (gt >= 0) ? inb[(size_t)(cc0 + kk) * Tn + gt] : 0.f);
        }
        __syncthreads();
#pragma unroll
        for (int r = 0; r < 3; r++) {
            wmma::fragment<wmma::matrix_a, 16, 16, 16, __nv_bfloat16, wmma::col_major> a;
            wmma::load_matrix_sync(a, &As[r][0][m_off], 72);
#pragma unroll
            for (int nf = 0; nf < 2; nf++) {
                wmma::fragment<wmma::matrix_b, 16, 16, 16, __nv_bfloat16, wmma::row_major> bf;
                wmma::load_matrix_sync(bf, &In3[r][0][n_base + nf * 16], 72);
                wmma::mma_sync(acc[nf], a, bf, acc[nf]);
            }
        }
        __syncthreads();
    }
    wmma::store_matrix_sync(&Ss[m_off][n_base], acc[0], 72, wmma::mem_row_major);
    wmma::store_matrix_sync(&Ss[m_off][n_base + 16], acc[1], 72, wmma::mem_row_major);
    __syncthreads();
    int row = tid >> 2, colb = (tid & 3) * 16;
    int o = o0 + row;
    float bo = bias[o];
    if (WHICH == 2) {
        const float* xrow = &x[((size_t)b * Cn + o) * Tn + t0 + colb];
        const float* wxp = &g_wx[b * Tn + t0 + colb];
        float* orow = &out[((size_t)b * Cn + o) * Tn + t0 + colb];
#pragma unroll
        for (int q = 0; q < 4; q++) {
            float4 xv = *(const float4*)&xrow[q * 4];
            float4 wx4 = *(const float4*)&wxp[q * 4];
            float4 res;
            float h0 = fmaxf(Ss[row][colb + q * 4 + 0] + bo, 0.f);
            float h1 = fmaxf(Ss[row][colb + q * 4 + 1] + bo, 0.f);
            float h2 = fmaxf(Ss[row][colb + q * 4 + 2] + bo, 0.f);
            float h3 = fmaxf(Ss[row][colb + q * 4 + 3] + bo, 0.f);
            res.x = fmaxf(h0 + xv.x + wx4.x * xv.x, 0.f);
            res.y = fmaxf(h1 + xv.y + wx4.y * xv.y, 0.f);
            res.z = fmaxf(h2 + xv.z + wx4.z * xv.z, 0.f);
            res.w = fmaxf(h3 + xv.w + wx4.w * xv.w, 0.f);
            *(float4*)&orow[q * 4] = res;
        }
    } else {
        float* orow = &out[((size_t)b * Cn + o) * Tn + t0 + colb];
#pragma unroll
        for (int q = 0; q < 4; q++) {
            float4 res;
            res.x = fmaxf(Ss[row][colb + q * 4 + 0] + bo, 0.f);
            res.y = fmaxf(Ss[row][colb + q * 4 + 1] + bo, 0.f);
            res.z = fmaxf(Ss[row][colb + q * 4 + 2] + bo, 0.f);
            res.w = fmaxf(Ss[row][colb + q * 4 + 3] + bo, 0.f);
            *(float4*)&orow[q * 4] = res;
        }
    }
}

// ---------------------------------------------------------------------------
extern "C" void kernel_launch(void* const* d_in, const int* in_sizes, int n_in,
                              void* d_out, int out_size) {
    const float* x   = (const float*)d_in[0];
    const float* Wq  = (const float*)d_in[1];
    const float* bq  = (const float*)d_in[2];
    const float* Wk  = (const float*)d_in[3];
    const float* bk  = (const float*)d_in[4];
    const float* Wv  = (const float*)d_in[5];
    const float* bv  = (const float*)d_in[6];
    const float* c1v = (const float*)d_in[7];
    const float* c1g = (const float*)d_in[8];
    const float* c1b = (const float*)d_in[9];
    const float* c2v = (const float*)d_in[10];
    const float* c2g = (const float*)d_in[11];
    const float* c2b = (const float*)d_in[12];
    float* out = (float*)d_out;

    wnorm_kernel<<<Cn, 256>>>(c1v, c1g, 0);
    wnorm_kernel<<<Cn, 256>>>(c2v, c2g, 1);

    gemm_qkv_wmma<<<dim3(Tn / 64, 12, Bn), 256>>>(x, Wq, bq, Wk, bk, Wv, bv);

    gemm_scores<<<dim3(136, 1, Bn), 256>>>();   // triangular tile grid
    invcol_kernel<<<(Bn * Tn) / 256, 256>>>();
    row_sum<<<dim3(Tn / 8, Bn), 256>>>();
    wx_softmax<<<Bn, 256>>>();
    gemm_av<<<dim3(Tn / 64, Cn / 64, Bn), 256>>>();

    conv_kernel<1><<<dim3(Tn / 64, Cn / 64, Bn), 256>>>(c1b, x, nullptr);
    conv_kernel<2><<<dim3(Tn / 64, Cn / 64, Bn), 256>>>(c2b, x, out);
}

// round 13
// speedup vs baseline: 1.6219x; 1.1067x over previous
#include <cuda_runtime.h>
#include <cuda_bf16.h>
#include <mma.h>
#include <cstdint>

using namespace nvcuda;

#define Bn   16
#define Cn   256
#define Tn   1024
#define KEYn 256
#define INV_SQRT_K 0.0625f

// ---------------- scratch (device globals; no allocation allowed) ----------
__device__ __nv_bfloat16 g_q[Bn * KEYn * Tn];    // channel-major [B,KEY,T] bf16
__device__ __nv_bfloat16 g_k[Bn * KEYn * Tn];    // channel-major [B,KEY,T] bf16
__device__ float g_v[Bn * Tn * Cn];              // token-major   [B,T,C]
__device__ __nv_bfloat16 g_attn[(size_t)Bn * Tn * Tn]; // exp(scores), bf16
__device__ float g_colpart[(size_t)16 * Bn * Tn];
__device__ float g_invcol[Bn * Tn];
__device__ float g_rowsum[Bn * Tn];
__device__ float g_wx[Bn * Tn];
__device__ float g_oa[Bn * Cn * Tn];
__device__ float g_h1[Bn * Cn * Tn];
__device__ __nv_bfloat16 g_ws1[3 * Cn * Cn];     // weight-normed bf16, [r][c][o]
__device__ __nv_bfloat16 g_ws2[3 * Cn * Cn];

// ---------------- weight norm -> split per-tap transposed bf16 layout ------
__global__ __launch_bounds__(256) void wnorm_kernel(const float* __restrict__ v,
                                                    const float* __restrict__ g,
                                                    int which) {
    __nv_bfloat16* w = which ? g_ws2 : g_ws1;
    int o = blockIdx.x;
    int tid = threadIdx.x;
    __shared__ float red[256];
    float s = 0.f;
    for (int i = tid; i < Cn * 3; i += 256) {
        float t = v[o * Cn * 3 + i];
        s += t * t;
    }
    red[tid] = s;
    __syncthreads();
    for (int st = 128; st > 0; st >>= 1) {
        if (tid < st) red[tid] += red[tid + st];
        __syncthreads();
    }
    float scale = g[o] * rsqrtf(red[0]);
    for (int i = tid; i < Cn * 3; i += 256) {
        int c = i / 3, r = i - c * 3;
        w[(r * Cn + c) * Cn + o] = __float2bfloat16(v[o * Cn * 3 + i] * scale);
    }
}

// helper: convert fragment floats to tf32 (RNE; also caps register liveness)
template <typename FragT>
__device__ __forceinline__ void to_tf32(FragT& f) {
#pragma unroll
    for (int i = 0; i < f.num_elements; i++) f.x[i] = wmma::__float_to_tf32(f.x[i]);
}

// ------- fused q/k/v projection (tf32 wmma, K-step 32, union smem) ---------
// q/k written as bf16 channel-major; v as fp32 token-major.
__global__ __launch_bounds__(256) void gemm_qkv_wmma(
        const float* __restrict__ x,
        const float* __restrict__ Wq, const float* __restrict__ bq,
        const float* __restrict__ Wk, const float* __restrict__ bk,
        const float* __restrict__ Wv, const float* __restrict__ bv) {
    int b = blockIdx.z;
    int t0 = blockIdx.x * 64;
    int by = blockIdx.y;
    int which = by >> 2;               // 0=q 1=k 2=v
    int n0 = (by & 3) * 64;
    const float* W = (which == 0) ? Wq : (which == 1) ? Wk : Wv;
    const float* bias = (which == 0) ? bq : (which == 1) ? bk : bv;
    int tid = threadIdx.x;
    __shared__ union {
        struct { float W[32][72]; float X[32][72]; } mi;
        float S[64][72];
    } sm;
    int wid = tid >> 5;
    int m_off = (wid & 3) * 16;        // n
    int n_base = (wid >> 2) * 32;      // t
    wmma::fragment<wmma::accumulator, 16, 16, 8, float> acc[2];
    wmma::fill_fragment(acc[0], 0.f);
    wmma::fill_fragment(acc[1], 0.f);
    const float* xb = x + (size_t)b * Cn * Tn;
    int lr = tid >> 4, lc = (tid & 15) * 4;
    for (int c0 = 0; c0 < Cn; c0 += 32) {
        *(float4*)&sm.mi.W[lr][lc]      = *(const float4*)&W[(c0 + lr) * 256 + n0 + lc];
        *(float4*)&sm.mi.W[lr + 16][lc] = *(const float4*)&W[(c0 + lr + 16) * 256 + n0 + lc];
        *(float4*)&sm.mi.X[lr][lc]      = *(const float4*)&xb[(size_t)(c0 + lr) * Tn + t0 + lc];
        *(float4*)&sm.mi.X[lr + 16][lc] = *(const float4*)&xb[(size_t)(c0 + lr + 16) * Tn + t0 + lc];
        __syncthreads();
#pragma unroll
        for (int ks = 0; ks < 32; ks += 8) {
            wmma::fragment<wmma::matrix_a, 16, 16, 8, wmma::precision::tf32, wmma::col_major> a;
            wmma::load_matrix_sync(a, &sm.mi.W[ks][m_off], 72);
#pragma unroll
            for (int nf = 0; nf < 2; nf++) {
                wmma::fragment<wmma::matrix_b, 16, 16, 8, wmma::precision::tf32, wmma::row_major> bf;
                wmma::load_matrix_sync(bf, &sm.mi.X[ks][n_base + nf * 16], 72);
                wmma::mma_sync(acc[nf], a, bf, acc[nf]);
            }
        }
        __syncthreads();
    }
    wmma::store_matrix_sync(&sm.S[m_off][n_base], acc[0], 72, wmma::mem_row_major);
    wmma::store_matrix_sync(&sm.S[m_off][n_base + 16], acc[1], 72, wmma::mem_row_major);
    __syncthreads();
    if (which < 2) {   // q/k: channel-major [n][t], bf16
        __nv_bfloat16* out = (which == 0) ? g_q : g_k;
        int row = tid >> 2, colb = (tid & 3) * 16;
        int n = n0 + row;
        float bo = bias[n];
        __nv_bfloat16* orow = &out[((size_t)b * KEYn + n) * Tn + t0 + colb];
#pragma unroll
        for (int q = 0; q < 4; q++) {
            *(__nv_bfloat162*)&orow[q * 4] = __floats2bfloat162_rn(
                sm.S[row][colb + q * 4 + 0] + bo, sm.S[row][colb + q * 4 + 1] + bo);
            *(__nv_bfloat162*)&orow[q * 4 + 2] = __floats2bfloat162_rn(
                sm.S[row][colb + q * 4 + 2] + bo, sm.S[row][colb + q * 4 + 3] + bo);
        }
    } else {           // v: token-major [t][c], fp32, transposed write via smem
        int col = tid >> 2;            // t index 0..63
        int rowb = (tid & 3) * 16;     // n chunk
#pragma unroll
        for (int q = 0; q < 4; q++) {
            float4 res;
            res.x = sm.S[rowb + q * 4 + 0][col] + bias[n0 + rowb + q * 4 + 0];
            res.y = sm.S[rowb + q * 4 + 1][col] + bias[n0 + rowb + q * 4 + 1];
            res.z = sm.S[rowb + q * 4 + 2][col] + bias[n0 + rowb + q * 4 + 2];
            res.w = sm.S[rowb + q * 4 + 3][col] + bias[n0 + rowb + q * 4 + 3];
            *(float4*)&g_v[((size_t)b * Tn + t0 + col) * Cn + n0 + rowb + q * 4] = res;
        }
    }
}

// ------- scores (bf16 wmma 16x16x16, triangular grid, K-step 32) -----------
__global__ __launch_bounds__(256) void gemm_scores() {
    int b = blockIdx.z;
    int idx = blockIdx.x;
    int jt = (int)((sqrtf(8.f * idx + 1.f) - 1.f) * 0.5f);
    while ((jt + 1) * (jt + 2) / 2 <= idx) jt++;
    while (jt * (jt + 1) / 2 > idx) jt--;
    int it = idx - jt * (jt + 1) / 2;
    int i0 = it * 64, j0 = jt * 64;
    int tid = threadIdx.x;
    __nv_bfloat16* S = g_attn + (size_t)b * Tn * Tn;
    float* cpart = g_colpart + (size_t)jt * Bn * Tn + b * Tn + i0;
    int c = tid & 63, rb = tid >> 6;
    __shared__ union {
        struct {
            alignas(16) __nv_bfloat16 Q[32][72];
            alignas(16) __nv_bfloat16 K[32][72];
        } mi;
        struct { float S[64][72]; float cred[4][64]; } ep;
    } sm;
    int wid = tid >> 5;
    int m_off = (wid & 3) * 16;
    int n_base = (wid >> 2) * 32;
    const __nv_bfloat16* qb = g_q + (size_t)b * KEYn * Tn;
    const __nv_bfloat16* kb = g_k + (size_t)b * KEYn * Tn;
    wmma::fragment<wmma::accumulator, 16, 16, 16, float> acc[2];
    wmma::fill_fragment(acc[0], 0.f);
    wmma::fill_fragment(acc[1], 0.f);
    int lr = tid >> 3, lc = (tid & 7) * 8;   // 32 rows x 64 bf16 per tile fill
    for (int kc = 0; kc < KEYn; kc += 32) {
        *(float4*)&sm.mi.Q[lr][lc] = *(const float4*)&qb[(size_t)(kc + lr) * Tn + j0 + lc];
        *(float4*)&sm.mi.K[lr][lc] = *(const float4*)&kb[(size_t)(kc + lr) * Tn + i0 + lc];
        __syncthreads();
#pragma unroll
        for (int ks = 0; ks < 32; ks += 16) {
            wmma::fragment<wmma::matrix_a, 16, 16, 16, __nv_bfloat16, wmma::col_major> a;
            wmma::load_matrix_sync(a, &sm.mi.Q[ks][m_off], 72);
#pragma unroll
            for (int nf = 0; nf < 2; nf++) {
                wmma::fragment<wmma::matrix_b, 16, 16, 16, __nv_bfloat16, wmma::row_major> bf;
                wmma::load_matrix_sync(bf, &sm.mi.K[ks][n_base + nf * 16], 72);
                wmma::mma_sync(acc[nf], a, bf, acc[nf]);
            }
        }
        __syncthreads();
    }
    wmma::store_matrix_sync(&sm.ep.S[m_off][n_base], acc[0], 72, wmma::mem_row_major);
    wmma::store_matrix_sync(&sm.ep.S[m_off][n_base + 16], acc[1], 72, wmma::mem_row_major);
    __syncthreads();
    float csum = 0.f;
#pragma unroll
    for (int rr = 0; rr < 16; rr++) {
        int row = rb * 16 + rr;
        int j = j0 + row, i = i0 + c;
        float e = (i <= j) ? __expf(sm.ep.S[row][c] * INV_SQRT_K) : 0.f;
        S[(size_t)j * Tn + i] = __float2bfloat16(e);
        csum += e;
    }
    sm.ep.cred[rb][c] = csum;
    __syncthreads();
    if (tid < 64) {
        float s = sm.ep.cred[0][tid] + sm.ep.cred[1][tid]
                + sm.ep.cred[2][tid] + sm.ep.cred[3][tid];
        cpart[tid] = s;
    }
}

// ------- invcol[b,i] = 1 / sum_{p >= i_tile} colpart[p][b,i] ---------------
__global__ __launch_bounds__(256) void invcol_kernel() {
    int idx = blockIdx.x * 256 + threadIdx.x;
    int i = idx & (Tn - 1);
    int p0 = i >> 6;
    float s = 0.f;
    for (int p = p0; p < 16; p++) s += g_colpart[(size_t)p * Bn * Tn + idx];
    g_invcol[idx] = 1.f / s;
}

// ------- rowsum[b,j] = sum_{i<=j} e[b,j,i] * invcol[b,i] -------------------
__global__ __launch_bounds__(256) void row_sum() {
    int b = blockIdx.y;
    int j = blockIdx.x * 8 + (threadIdx.x >> 5);
    int lane = threadIdx.x & 31;
    const __nv_bfloat16* row = g_attn + (size_t)b * Tn * Tn + (size_t)j * Tn;
    const float* inv = g_invcol + b * Tn;
    float s = 0.f;
    for (int i = lane; i <= j; i += 32) s += __bfloat162float(row[i]) * inv[i];
#pragma unroll
    for (int o = 16; o > 0; o >>= 1) s += __shfl_xor_sync(0xffffffffu, s, o);
    if (lane == 0) g_rowsum[b * Tn + j] = s;
}

// ------- weight_x[b,:] = softmax_j(rowsum[b,:]) ----------------------------
__global__ __launch_bounds__(256) void wx_softmax() {
    int b = blockIdx.x;
    int tid = threadIdx.x;
    __shared__ float red[256];
    const float* r = g_rowsum + b * Tn;
    float m = -1e30f;
    for (int j = tid; j < Tn; j += 256) m = fmaxf(m, r[j]);
    red[tid] = m;
    __syncthreads();
    for (int st = 128; st > 0; st >>= 1) {
        if (tid < st) red[tid] = fmaxf(red[tid], red[tid + st]);
        __syncthreads();
    }
    m = red[0];
    __syncthreads();
    float sum = 0.f;
    for (int j = tid; j < Tn; j += 256) sum += __expf(r[j] - m);
    red[tid] = sum;
    __syncthreads();
    for (int st = 128; st > 0; st >>= 1) {
        if (tid < st) red[tid] += red[tid + st];
        __syncthreads();
    }
    float inv = 1.f / red[0];
    for (int j = tid; j < Tn; j += 256)
        g_wx[b * Tn + j] = __expf(r[j] - m) * inv;
}

// ------- attn·V (bf16 wmma 16x16x16): oa = sum_i e[j,i]*invcol[i]*v[i,c] ---
__global__ __launch_bounds__(256) void gemm_av() {
    int b = blockIdx.z;
    int j0 = blockIdx.x * 64, c0 = blockIdx.y * 64;
    int tid = threadIdx.x;
    __shared__ alignas(16) __nv_bfloat16 As[16][72];   // [i][c] scaled v
    __shared__ alignas(16) __nv_bfloat16 Es[64][24];   // [j][i-chunk]
    const __nv_bfloat16* A = g_attn + (size_t)b * Tn * Tn;
    const float* V = g_v + (size_t)b * Tn * Cn;
    const float* inv = g_invcol + b * Tn;
    int wid = tid >> 5;
    int m_off = (wid & 3) * 16;          // c
    int n_base = (wid >> 2) * 32;        // j
    wmma::fragment<wmma::accumulator, 16, 16, 16, float> acc[2];
    wmma::fill_fragment(acc[0], 0.f);
    wmma::fill_fragment(acc[1], 0.f);
    int ar = tid >> 4, ac = (tid & 15) * 4;
    int er = tid >> 2, ec = (tid & 3) * 4;
    int kend = j0 + 64;
    for (int ii = 0; ii < kend; ii += 16) {
        float sc = inv[ii + ar];
        float4 v4 = *(const float4*)&V[(size_t)(ii + ar) * Cn + c0 + ac];
        *(__nv_bfloat162*)&As[ar][ac] =
            __floats2bfloat162_rn(v4.x * sc, v4.y * sc);
        *(__nv_bfloat162*)&As[ar][ac + 2] =
            __floats2bfloat162_rn(v4.z * sc, v4.w * sc);
        *(float2*)&Es[er][ec] = *(const float2*)&A[(size_t)(j0 + er) * Tn + ii + ec];
        __syncthreads();
        wmma::fragment<wmma::matrix_a, 16, 16, 16, __nv_bfloat16, wmma::col_major> a;
        wmma::load_matrix_sync(a, &As[0][m_off], 72);
#pragma unroll
        for (int nf = 0; nf < 2; nf++) {
            wmma::fragment<wmma::matrix_b, 16, 16, 16, __nv_bfloat16, wmma::col_major> bf;
            wmma::load_matrix_sync(bf, &Es[n_base + nf * 16][0], 24);
            wmma::mma_sync(acc[nf], a, bf, acc[nf]);
        }
        __syncthreads();
    }
    float* obase = &g_oa[((size_t)b * Cn + c0 + m_off) * Tn + j0];
    wmma::store_matrix_sync(obase + n_base, acc[0], Tn, wmma::mem_row_major);
    wmma::store_matrix_sync(obase + n_base + 16, acc[1], Tn, wmma::mem_row_major);
}

// ------- causal conv (bf16 wmma 16x16x16 implicit GEMM, KS=3) + fusion -----
template <int WHICH>
__global__ __launch_bounds__(256) void conv_kernel(const float* __restrict__ bias,
                                                   const float* __restrict__ x,
                                                   float* __restrict__ out_final) {
    const float* in = (WHICH == 1) ? g_oa : g_h1;
    const __nv_bfloat16* w = (WHICH == 1) ? g_ws1 : g_ws2;
    float* out = (WHICH == 1) ? g_h1 : out_final;
    int b = blockIdx.z;
    int t0 = blockIdx.x * 64, o0 = blockIdx.y * 64;
    int tid = threadIdx.x;
    __shared__ alignas(16) __nv_bfloat16 As[3][16][72];   // [r][c][o]
    __shared__ alignas(16) __nv_bfloat16 In3[3][16][72];  // [r][c][t per tap]
    __shared__ float Ss[64][72];
    int wid = tid >> 5;
    int m_off = (wid & 3) * 16;       // o
    int n_base = (wid >> 2) * 32;     // t
    wmma::fragment<wmma::accumulator, 16, 16, 16, float> acc[2];
    wmma::fill_fragment(acc[0], 0.f);
    wmma::fill_fragment(acc[1], 0.f);
    const float* inb = in + (size_t)b * Cn * Tn;
    for (int cc0 = 0; cc0 < Cn; cc0 += 16) {
#pragma unroll
        for (int q = 0; q < 3; q++) {
            int lin = tid + q * 256;          // 0..767
            int row = lin >> 4;               // 0..47
            int r = row >> 4, kk = row & 15;
            int col = (lin & 15) * 4;
            *(float2*)&As[r][kk][col] =
                *(const float2*)&w[((r * Cn) + cc0 + kk) * Cn + o0 + col];
        }
#pragma unroll
        for (int q = 0; q < 12; q++) {
            int lin = tid + q * 256;          // 0..3071
            int r = lin >> 10;
            int rem = lin & 1023;
            int kk = rem >> 6, col = rem & 63;
            int gt = t0 + col - 2 + r;
            In3[r][kk][col] = __float2bfloat16(
                (gt >= 0) ? inb[(size_t)(cc0 + kk) * Tn + gt] : 0.f);
        }
        __syncthreads();
#pragma unroll
        for (int r = 0; r < 3; r++) {
            wmma::fragment<wmma::matrix_a, 16, 16, 16, __nv_bfloat16, wmma::col_major> a;
            wmma::load_matrix_sync(a, &As[r][0][m_off], 72);
#pragma unroll
            for (int nf = 0; nf < 2; nf++) {
                wmma::fragment<wmma::matrix_b, 16, 16, 16, __nv_bfloat16, wmma::row_major> bf;
                wmma::load_matrix_sync(bf, &In3[r][0][n_base + nf * 16], 72);
                wmma::mma_sync(acc[nf], a, bf, acc[nf]);
            }
        }
        __syncthreads();
    }
    wmma::store_matrix_sync(&Ss[m_off][n_base], acc[0], 72, wmma::mem_row_major);
    wmma::store_matrix_sync(&Ss[m_off][n_base + 16], acc[1], 72, wmma::mem_row_major);
    __syncthreads();
    int row = tid >> 2, colb = (tid & 3) * 16;
    int o = o0 + row;
    float bo = bias[o];
    if (WHICH == 2) {
        const float* xrow = &x[((size_t)b * Cn + o) * Tn + t0 + colb];
        const float* wxp = &g_wx[b * Tn + t0 + colb];
        float* orow = &out[((size_t)b * Cn + o) * Tn + t0 + colb];
#pragma unroll
        for (int q = 0; q < 4; q++) {
            float4 xv = *(const float4*)&xrow[q * 4];
            float4 wx4 = *(const float4*)&wxp[q * 4];
            float4 res;
            float h0 = fmaxf(Ss[row][colb + q * 4 + 0] + bo, 0.f);
            float h1 = fmaxf(Ss[row][colb + q * 4 + 1] + bo, 0.f);
            float h2 = fmaxf(Ss[row][colb + q * 4 + 2] + bo, 0.f);
            float h3 = fmaxf(Ss[row][colb + q * 4 + 3] + bo, 0.f);
            res.x = fmaxf(h0 + xv.x + wx4.x * xv.x, 0.f);
            res.y = fmaxf(h1 + xv.y + wx4.y * xv.y, 0.f);
            res.z = fmaxf(h2 + xv.z + wx4.z * xv.z, 0.f);
            res.w = fmaxf(h3 + xv.w + wx4.w * xv.w, 0.f);
            *(float4*)&orow[q * 4] = res;
        }
    } else {
        float* orow = &out[((size_t)b * Cn + o) * Tn + t0 + colb];
#pragma unroll
        for (int q = 0; q < 4; q++) {
            float4 res;
            res.x = fmaxf(Ss[row][colb + q * 4 + 0] + bo, 0.f);
            res.y = fmaxf(Ss[row][colb + q * 4 + 1] + bo, 0.f);
            res.z = fmaxf(Ss[row][colb + q * 4 + 2] + bo, 0.f);
            res.w = fmaxf(Ss[row][colb + q * 4 + 3] + bo, 0.f);
            *(float4*)&orow[q * 4] = res;
        }
    }
}

// ---------------------------------------------------------------------------
extern "C" void kernel_launch(void* const* d_in, const int* in_sizes, int n_in,
                              void* d_out, int out_size) {
    const float* x   = (const float*)d_in[0];
    const float* Wq  = (const float*)d_in[1];
    const float* bq  = (const float*)d_in[2];
    const float* Wk  = (const float*)d_in[3];
    const float* bk  = (const float*)d_in[4];
    const float* Wv  = (const float*)d_in[5];
    const float* bv  = (const float*)d_in[6];
    const float* c1v = (const float*)d_in[7];
    const float* c1g = (const float*)d_in[8];
    const float* c1b = (const float*)d_in[9];
    const float* c2v = (const float*)d_in[10];
    const float* c2g = (const float*)d_in[11];
    const float* c2b = (const float*)d_in[12];
    float* out = (float*)d_out;

    wnorm_kernel<<<Cn, 256>>>(c1v, c1g, 0);
    wnorm_kernel<<<Cn, 256>>>(c2v, c2g, 1);

    gemm_qkv_wmma<<<dim3(Tn / 64, 12, Bn), 256>>>(x, Wq, bq, Wk, bk, Wv, bv);

    gemm_scores<<<dim3(136, 1, Bn), 256>>>();   // triangular tile grid
    invcol_kernel<<<(Bn * Tn) / 256, 256>>>();
    row_sum<<<dim3(Tn / 8, Bn), 256>>>();
    wx_softmax<<<Bn, 256>>>();
    gemm_av<<<dim3(Tn / 64, Cn / 64, Bn), 256>>>();

    conv_kernel<1><<<dim3(Tn / 64, Cn / 64, Bn), 256>>>(c1b, x, nullptr);
    conv_kernel<2><<<dim3(Tn / 64, Cn / 64, Bn), 256>>>(c2b, x, out);
}

// round 14
// speedup vs baseline: 1.8084x; 1.1150x over previous
#include <cuda_runtime.h>
#include <cuda_bf16.h>
#include <mma.h>
#include <cstdint>

using namespace nvcuda;

#define Bn   16
#define Cn   256
#define Tn   1024
#define KEYn 256
#define INV_SQRT_K 0.0625f

// ---------------- scratch (device globals; no allocation allowed) ----------
__device__ __nv_bfloat16 g_q[Bn * KEYn * Tn];    // channel-major [B,KEY,T] bf16
__device__ __nv_bfloat16 g_k[Bn * KEYn * Tn];    // channel-major [B,KEY,T] bf16
__device__ float g_v[Bn * Tn * Cn];              // token-major   [B,T,C]
__device__ __nv_bfloat16 g_attn[(size_t)Bn * Tn * Tn]; // exp(scores), bf16
__device__ float g_colpart[(size_t)16 * Bn * Tn];
__device__ float g_invcol[Bn * Tn];
__device__ float g_rowsum[Bn * Tn];
__device__ float g_wx[Bn * Tn];
__device__ __nv_bfloat16 g_oa[Bn * Cn * Tn];     // attention out, bf16
__device__ __nv_bfloat16 g_h1[Bn * Cn * Tn];     // conv1 out, bf16
__device__ __nv_bfloat16 g_ws1[3 * Cn * Cn];     // weight-normed bf16, [r][c][o]
__device__ __nv_bfloat16 g_ws2[3 * Cn * Cn];

// ---------------- weight norm -> split per-tap transposed bf16 layout ------
__global__ __launch_bounds__(256) void wnorm_kernel(const float* __restrict__ v,
                                                    const float* __restrict__ g,
                                                    int which) {
    __nv_bfloat16* w = which ? g_ws2 : g_ws1;
    int o = blockIdx.x;
    int tid = threadIdx.x;
    __shared__ float red[256];
    float s = 0.f;
    for (int i = tid; i < Cn * 3; i += 256) {
        float t = v[o * Cn * 3 + i];
        s += t * t;
    }
    red[tid] = s;
    __syncthreads();
    for (int st = 128; st > 0; st >>= 1) {
        if (tid < st) red[tid] += red[tid + st];
        __syncthreads();
    }
    float scale = g[o] * rsqrtf(red[0]);
    for (int i = tid; i < Cn * 3; i += 256) {
        int c = i / 3, r = i - c * 3;
        w[(r * Cn + c) * Cn + o] = __float2bfloat16(v[o * Cn * 3 + i] * scale);
    }
}

// ------- fused q/k/v projection (bf16 wmma 16x16x16, K-step 32) ------------
// q/k written as bf16 channel-major; v as fp32 token-major.
__global__ __launch_bounds__(256) void gemm_qkv_wmma(
        const float* __restrict__ x,
        const float* __restrict__ Wq, const float* __restrict__ bq,
        const float* __restrict__ Wk, const float* __restrict__ bk,
        const float* __restrict__ Wv, const float* __restrict__ bv) {
    int b = blockIdx.z;
    int t0 = blockIdx.x * 64;
    int by = blockIdx.y;
    int which = by >> 2;               // 0=q 1=k 2=v
    int n0 = (by & 3) * 64;
    const float* W = (which == 0) ? Wq : (which == 1) ? Wk : Wv;
    const float* bias = (which == 0) ? bq : (which == 1) ? bk : bv;
    int tid = threadIdx.x;
    __shared__ union {
        struct {
            alignas(16) __nv_bfloat16 W[32][72];
            alignas(16) __nv_bfloat16 X[32][72];
        } mi;
        float S[64][72];
    } sm;
    int wid = tid >> 5;
    int m_off = (wid & 3) * 16;        // n
    int n_base = (wid >> 2) * 32;      // t
    wmma::fragment<wmma::accumulator, 16, 16, 16, float> acc[2];
    wmma::fill_fragment(acc[0], 0.f);
    wmma::fill_fragment(acc[1], 0.f);
    const float* xb = x + (size_t)b * Cn * Tn;
    int lr = tid >> 4, lc = (tid & 15) * 4;
    for (int c0 = 0; c0 < Cn; c0 += 32) {
#pragma unroll
        for (int h = 0; h < 2; h++) {
            float4 wv = *(const float4*)&W[(c0 + lr + h * 16) * 256 + n0 + lc];
            *(__nv_bfloat162*)&sm.mi.W[lr + h * 16][lc] = __floats2bfloat162_rn(wv.x, wv.y);
            *(__nv_bfloat162*)&sm.mi.W[lr + h * 16][lc + 2] = __floats2bfloat162_rn(wv.z, wv.w);
            float4 xv = *(const float4*)&xb[(size_t)(c0 + lr + h * 16) * Tn + t0 + lc];
            *(__nv_bfloat162*)&sm.mi.X[lr + h * 16][lc] = __floats2bfloat162_rn(xv.x, xv.y);
            *(__nv_bfloat162*)&sm.mi.X[lr + h * 16][lc + 2] = __floats2bfloat162_rn(xv.z, xv.w);
        }
        __syncthreads();
#pragma unroll
        for (int ks = 0; ks < 32; ks += 16) {
            wmma::fragment<wmma::matrix_a, 16, 16, 16, __nv_bfloat16, wmma::col_major> a;
            wmma::load_matrix_sync(a, &sm.mi.W[ks][m_off], 72);
#pragma unroll
            for (int nf = 0; nf < 2; nf++) {
                wmma::fragment<wmma::matrix_b, 16, 16, 16, __nv_bfloat16, wmma::row_major> bf;
                wmma::load_matrix_sync(bf, &sm.mi.X[ks][n_base + nf * 16], 72);
                wmma::mma_sync(acc[nf], a, bf, acc[nf]);
            }
        }
        __syncthreads();
    }
    wmma::store_matrix_sync(&sm.S[m_off][n_base], acc[0], 72, wmma::mem_row_major);
    wmma::store_matrix_sync(&sm.S[m_off][n_base + 16], acc[1], 72, wmma::mem_row_major);
    __syncthreads();
    if (which < 2) {   // q/k: channel-major [n][t], bf16
        __nv_bfloat16* out = (which == 0) ? g_q : g_k;
        int row = tid >> 2, colb = (tid & 3) * 16;
        int n = n0 + row;
        float bo = bias[n];
        __nv_bfloat16* orow = &out[((size_t)b * KEYn + n) * Tn + t0 + colb];
#pragma unroll
        for (int q = 0; q < 4; q++) {
            *(__nv_bfloat162*)&orow[q * 4] = __floats2bfloat162_rn(
                sm.S[row][colb + q * 4 + 0] + bo, sm.S[row][colb + q * 4 + 1] + bo);
            *(__nv_bfloat162*)&orow[q * 4 + 2] = __floats2bfloat162_rn(
                sm.S[row][colb + q * 4 + 2] + bo, sm.S[row][colb + q * 4 + 3] + bo);
        }
    } else {           // v: token-major [t][c], fp32, transposed write via smem
        int col = tid >> 2;            // t index 0..63
        int rowb = (tid & 3) * 16;     // n chunk
#pragma unroll
        for (int q = 0; q < 4; q++) {
            float4 res;
            res.x = sm.S[rowb + q * 4 + 0][col] + bias[n0 + rowb + q * 4 + 0];
            res.y = sm.S[rowb + q * 4 + 1][col] + bias[n0 + rowb + q * 4 + 1];
            res.z = sm.S[rowb + q * 4 + 2][col] + bias[n0 + rowb + q * 4 + 2];
            res.w = sm.S[rowb + q * 4 + 3][col] + bias[n0 + rowb + q * 4 + 3];
            *(float4*)&g_v[((size_t)b * Tn + t0 + col) * Cn + n0 + rowb + q * 4] = res;
        }
    }
}

// ------- scores (bf16 wmma 16x16x16, triangular grid, K-step 32) -----------
__global__ __launch_bounds__(256) void gemm_scores() {
    int b = blockIdx.z;
    int idx = blockIdx.x;
    int jt = (int)((sqrtf(8.f * idx + 1.f) - 1.f) * 0.5f);
    while ((jt + 1) * (jt + 2) / 2 <= idx) jt++;
    while (jt * (jt + 1) / 2 > idx) jt--;
    int it = idx - jt * (jt + 1) / 2;
    int i0 = it * 64, j0 = jt * 64;
    int tid = threadIdx.x;
    __nv_bfloat16* S = g_attn + (size_t)b * Tn * Tn;
    float* cpart = g_colpart + (size_t)jt * Bn * Tn + b * Tn + i0;
    int c = tid & 63, rb = tid >> 6;
    __shared__ union {
        struct {
            alignas(16) __nv_bfloat16 Q[32][72];
            alignas(16) __nv_bfloat16 K[32][72];
        } mi;
        struct { float S[64][72]; float cred[4][64]; } ep;
    } sm;
    int wid = tid >> 5;
    int m_off = (wid & 3) * 16;
    int n_base = (wid >> 2) * 32;
    const __nv_bfloat16* qb = g_q + (size_t)b * KEYn * Tn;
    const __nv_bfloat16* kb = g_k + (size_t)b * KEYn * Tn;
    wmma::fragment<wmma::accumulator, 16, 16, 16, float> acc[2];
    wmma::fill_fragment(acc[0], 0.f);
    wmma::fill_fragment(acc[1], 0.f);
    int lr = tid >> 3, lc = (tid & 7) * 8;   // 32 rows x 64 bf16 per tile fill
    for (int kc = 0; kc < KEYn; kc += 32) {
        *(float4*)&sm.mi.Q[lr][lc] = *(const float4*)&qb[(size_t)(kc + lr) * Tn + j0 + lc];
        *(float4*)&sm.mi.K[lr][lc] = *(const float4*)&kb[(size_t)(kc + lr) * Tn + i0 + lc];
        __syncthreads();
#pragma unroll
        for (int ks = 0; ks < 32; ks += 16) {
            wmma::fragment<wmma::matrix_a, 16, 16, 16, __nv_bfloat16, wmma::col_major> a;
            wmma::load_matrix_sync(a, &sm.mi.Q[ks][m_off], 72);
#pragma unroll
            for (int nf = 0; nf < 2; nf++) {
                wmma::fragment<wmma::matrix_b, 16, 16, 16, __nv_bfloat16, wmma::row_major> bf;
                wmma::load_matrix_sync(bf, &sm.mi.K[ks][n_base + nf * 16], 72);
                wmma::mma_sync(acc[nf], a, bf, acc[nf]);
            }
        }
        __syncthreads();
    }
    wmma::store_matrix_sync(&sm.ep.S[m_off][n_base], acc[0], 72, wmma::mem_row_major);
    wmma::store_matrix_sync(&sm.ep.S[m_off][n_base + 16], acc[1], 72, wmma::mem_row_major);
    __syncthreads();
    float csum = 0.f;
#pragma unroll
    for (int rr = 0; rr < 16; rr++) {
        int row = rb * 16 + rr;
        int j = j0 + row, i = i0 + c;
        float e = (i <= j) ? __expf(sm.ep.S[row][c] * INV_SQRT_K) : 0.f;
        S[(size_t)j * Tn + i] = __float2bfloat16(e);
        csum += e;
    }
    sm.ep.cred[rb][c] = csum;
    __syncthreads();
    if (tid < 64) {
        float s = sm.ep.cred[0][tid] + sm.ep.cred[1][tid]
                + sm.ep.cred[2][tid] + sm.ep.cred[3][tid];
        cpart[tid] = s;
    }
}

// ------- invcol[b,i] = 1 / sum_{p >= i_tile} colpart[p][b,i] ---------------
__global__ __launch_bounds__(256) void invcol_kernel() {
    int idx = blockIdx.x * 256 + threadIdx.x;
    int i = idx & (Tn - 1);
    int p0 = i >> 6;
    float s = 0.f;
    for (int p = p0; p < 16; p++) s += g_colpart[(size_t)p * Bn * Tn + idx];
    g_invcol[idx] = 1.f / s;
}

// ------- rowsum[b,j] = sum_{i<=j} e[b,j,i] * invcol[b,i] -------------------
__global__ __launch_bounds__(256) void row_sum() {
    int b = blockIdx.y;
    int j = blockIdx.x * 8 + (threadIdx.x >> 5);
    int lane = threadIdx.x & 31;
    const __nv_bfloat16* row = g_attn + (size_t)b * Tn * Tn + (size_t)j * Tn;
    const float* inv = g_invcol + b * Tn;
    float s = 0.f;
    for (int i = lane; i <= j; i += 32) s += __bfloat162float(row[i]) * inv[i];
#pragma unroll
    for (int o = 16; o > 0; o >>= 1) s += __shfl_xor_sync(0xffffffffu, s, o);
    if (lane == 0) g_rowsum[b * Tn + j] = s;
}

// ------- weight_x[b,:] = softmax_j(rowsum[b,:]) ----------------------------
__global__ __launch_bounds__(256) void wx_softmax() {
    int b = blockIdx.x;
    int tid = threadIdx.x;
    __shared__ float red[256];
    const float* r = g_rowsum + b * Tn;
    float m = -1e30f;
    for (int j = tid; j < Tn; j += 256) m = fmaxf(m, r[j]);
    red[tid] = m;
    __syncthreads();
    for (int st = 128; st > 0; st >>= 1) {
        if (tid < st) red[tid] = fmaxf(red[tid], red[tid + st]);
        __syncthreads();
    }
    m = red[0];
    __syncthreads();
    float sum = 0.f;
    for (int j = tid; j < Tn; j += 256) sum += __expf(r[j] - m);
    red[tid] = sum;
    __syncthreads();
    for (int st = 128; st > 0; st >>= 1) {
        if (tid < st) red[tid] += red[tid + st];
        __syncthreads();
    }
    float inv = 1.f / red[0];
    for (int j = tid; j < Tn; j += 256)
        g_wx[b * Tn + j] = __expf(r[j] - m) * inv;
}

// ------- attn·V (bf16 wmma 16x16x16), bf16 output via smem staging ---------
__global__ __launch_bounds__(256) void gemm_av() {
    int b = blockIdx.z;
    int j0 = blockIdx.x * 64, c0 = blockIdx.y * 64;
    int tid = threadIdx.x;
    __shared__ alignas(16) __nv_bfloat16 As[16][72];   // [i][c] scaled v
    __shared__ alignas(16) __nv_bfloat16 Es[64][24];   // [j][i-chunk]
    __shared__ float Ss[64][72];                       // [c][j] staging
    const __nv_bfloat16* A = g_attn + (size_t)b * Tn * Tn;
    const float* V = g_v + (size_t)b * Tn * Cn;
    const float* inv = g_invcol + b * Tn;
    int wid = tid >> 5;
    int m_off = (wid & 3) * 16;          // c
    int n_base = (wid >> 2) * 32;        // j
    wmma::fragment<wmma::accumulator, 16, 16, 16, float> acc[2];
    wmma::fill_fragment(acc[0], 0.f);
    wmma::fill_fragment(acc[1], 0.f);
    int ar = tid >> 4, ac = (tid & 15) * 4;
    int er = tid >> 2, ec = (tid & 3) * 4;
    int kend = j0 + 64;
    for (int ii = 0; ii < kend; ii += 16) {
        float sc = inv[ii + ar];
        float4 v4 = *(const float4*)&V[(size_t)(ii + ar) * Cn + c0 + ac];
        *(__nv_bfloat162*)&As[ar][ac] =
            __floats2bfloat162_rn(v4.x * sc, v4.y * sc);
        *(__nv_bfloat162*)&As[ar][ac + 2] =
            __floats2bfloat162_rn(v4.z * sc, v4.w * sc);
        *(float2*)&Es[er][ec] = *(const float2*)&A[(size_t)(j0 + er) * Tn + ii + ec];
        __syncthreads();
        wmma::fragment<wmma::matrix_a, 16, 16, 16, __nv_bfloat16, wmma::col_major> a;
        wmma::load_matrix_sync(a, &As[0][m_off], 72);
#pragma unroll
        for (int nf = 0; nf < 2; nf++) {
            wmma::fragment<wmma::matrix_b, 16, 16, 16, __nv_bfloat16, wmma::col_major> bf;
            wmma::load_matrix_sync(bf, &Es[n_base + nf * 16][0], 24);
            wmma::mma_sync(acc[nf], a, bf, acc[nf]);
        }
        __syncthreads();
    }
    wmma::store_matrix_sync(&Ss[m_off][n_base], acc[0], 72, wmma::mem_row_major);
    wmma::store_matrix_sync(&Ss[m_off][n_base + 16], acc[1], 72, wmma::mem_row_major);
    __syncthreads();
    int row = tid >> 2, colb = (tid & 3) * 16;
    __nv_bfloat16* orow = &g_oa[((size_t)b * Cn + c0 + row) * Tn + j0 + colb];
#pragma unroll
    for (int q = 0; q < 4; q++) {
        *(__nv_bfloat162*)&orow[q * 4] = __floats2bfloat162_rn(
            Ss[row][colb + q * 4 + 0], Ss[row][colb + q * 4 + 1]);
        *(__nv_bfloat162*)&orow[q * 4 + 2] = __floats2bfloat162_rn(
            Ss[row][colb + q * 4 + 2], Ss[row][colb + q * 4 + 3]);
    }
}

// ------- causal conv (bf16 wmma 16x16x16 implicit GEMM, KS=3) + fusion -----
// WHICH==1: in=g_oa(bf16) -> out g_h1(bf16); WHICH==2: in=g_h1 -> fp32 final
template <int WHICH>
__global__ __launch_bounds__(256) void conv_kernel(const float* __restrict__ bias,
                                                   const float* __restrict__ x,
                                                   float* __restrict__ out_final) {
    const __nv_bfloat16* in = (WHICH == 1) ? g_oa : g_h1;
    const __nv_bfloat16* w = (WHICH == 1) ? g_ws1 : g_ws2;
    int b = blockIdx.z;
    int t0 = blockIdx.x * 64, o0 = blockIdx.y * 64;
    int tid = threadIdx.x;
    __shared__ alignas(16) __nv_bfloat16 As[3][16][72];   // [r][c][o]
    __shared__ alignas(16) __nv_bfloat16 In3[3][16][72];  // [r][c][t per tap]
    __shared__ float Ss[64][72];
    int wid = tid >> 5;
    int m_off = (wid & 3) * 16;       // o
    int n_base = (wid >> 2) * 32;     // t
    wmma::fragment<wmma::accumulator, 16, 16, 16, float> acc[2];
    wmma::fill_fragment(acc[0], 0.f);
    wmma::fill_fragment(acc[1], 0.f);
    const __nv_bfloat16* inb = in + (size_t)b * Cn * Tn;
    const __nv_bfloat16 zero_bf = __float2bfloat16(0.f);
    for (int cc0 = 0; cc0 < Cn; cc0 += 16) {
#pragma unroll
        for (int q = 0; q < 3; q++) {
            int lin = tid + q * 256;          // 0..767
            int row = lin >> 4;               // 0..47
            int r = row >> 4, kk = row & 15;
            int col = (lin & 15) * 4;
            *(float2*)&As[r][kk][col] =
                *(const float2*)&w[((r * Cn) + cc0 + kk) * Cn + o0 + col];
        }
#pragma unroll
        for (int q = 0; q < 12; q++) {
            int lin = tid + q * 256;          // 0..3071
            int r = lin >> 10;
            int rem = lin & 1023;
            int kk = rem >> 6, col = rem & 63;
            int gt = t0 + col - 2 + r;
            In3[r][kk][col] = (gt >= 0)
                ? inb[(size_t)(cc0 + kk) * Tn + gt] : zero_bf;
        }
        __syncthreads();
#pragma unroll
        for (int r = 0; r < 3; r++) {
            wmma::fragment<wmma::matrix_a, 16, 16, 16, __nv_bfloat16, wmma::col_major> a;
            wmma::load_matrix_sync(a, &As[r][0][m_off], 72);
#pragma unroll
            for (int nf = 0; nf < 2; nf++) {
                wmma::fragment<wmma::matrix_b, 16, 16, 16, __nv_bfloat16, wmma::row_major> bf;
                wmma::load_matrix_sync(bf, &In3[r][0][n_base + nf * 16], 72);
                wmma::mma_sync(acc[nf], a, bf, acc[nf]);
            }
        }
        __syncthreads();
    }
    wmma::store_matrix_sync(&Ss[m_off][n_base], acc[0], 72, wmma::mem_row_major);
    wmma::store_matrix_sync(&Ss[m_off][n_base + 16], acc[1], 72, wmma::mem_row_major);
    __syncthreads();
    int row = tid >> 2, colb = (tid & 3) * 16;
    int o = o0 + row;
    float bo = bias[o];
    if (WHICH == 2) {
        const float* xrow = &x[((size_t)b * Cn + o) * Tn + t0 + colb];
        const float* wxp = &g_wx[b * Tn + t0 + colb];
        float* orow = &out_final[((size_t)b * Cn + o) * Tn + t0 + colb];
#pragma unroll
        for (int q = 0; q < 4; q++) {
            float4 xv = *(const float4*)&xrow[q * 4];
            float4 wx4 = *(const float4*)&wxp[q * 4];
            float4 res;
            float h0 = fmaxf(Ss[row][colb + q * 4 + 0] + bo, 0.f);
            float h1 = fmaxf(Ss[row][colb + q * 4 + 1] + bo, 0.f);
            float h2 = fmaxf(Ss[row][colb + q * 4 + 2] + bo, 0.f);
            float h3 = fmaxf(Ss[row][colb + q * 4 + 3] + bo, 0.f);
            res.x = fmaxf(h0 + xv.x + wx4.x * xv.x, 0.f);
            res.y = fmaxf(h1 + xv.y + wx4.y * xv.y, 0.f);
            res.z = fmaxf(h2 + xv.z + wx4.z * xv.z, 0.f);
            res.w = fmaxf(h3 + xv.w + wx4.w * xv.w, 0.f);
            *(float4*)&orow[q * 4] = res;
        }
    } else {
        __nv_bfloat16* orow = &g_h1[((size_t)b * Cn + o) * Tn + t0 + colb];
#pragma unroll
        for (int q = 0; q < 4; q++) {
            *(__nv_bfloat162*)&orow[q * 4] = __floats2bfloat162_rn(
                fmaxf(Ss[row][colb + q * 4 + 0] + bo, 0.f),
                fmaxf(Ss[row][colb + q * 4 + 1] + bo, 0.f));
            *(__nv_bfloat162*)&orow[q * 4 + 2] = __floats2bfloat162_rn(
                fmaxf(Ss[row][colb + q * 4 + 2] + bo, 0.f),
                fmaxf(Ss[row][colb + q * 4 + 3] + bo, 0.f));
        }
    }
}

// ---------------------------------------------------------------------------
extern "C" void kernel_launch(void* const* d_in, const int* in_sizes, int n_in,
                              void* d_out, int out_size) {
    const float* x   = (const float*)d_in[0];
    const float* Wq  = (const float*)d_in[1];
    const float* bq  = (const float*)d_in[2];
    const float* Wk  = (const float*)d_in[3];
    const float* bk  = (const float*)d_in[4];
    const float* Wv  = (const float*)d_in[5];
    const float* bv  = (const float*)d_in[6];
    const float* c1v = (const float*)d_in[7];
    const float* c1g = (const float*)d_in[8];
    const float* c1b = (const float*)d_in[9];
    const float* c2v = (const float*)d_in[10];
    const float* c2g = (const float*)d_in[11];
    const float* c2b = (const float*)d_in[12];
    float* out = (float*)d_out;

    wnorm_kernel<<<Cn, 256>>>(c1v, c1g, 0);
    wnorm_kernel<<<Cn, 256>>>(c2v, c2g, 1);

    gemm_qkv_wmma<<<dim3(Tn / 64, 12, Bn), 256>>>(x, Wq, bq, Wk, bk, Wv, bv);

    gemm_scores<<<dim3(136, 1, Bn), 256>>>();   // triangular tile grid
    invcol_kernel<<<(Bn * Tn) / 256, 256>>>();
    row_sum<<<dim3(Tn / 8, Bn), 256>>>();
    wx_softmax<<<Bn, 256>>>();
    gemm_av<<<dim3(Tn / 64, Cn / 64, Bn), 256>>>();

    conv_kernel<1><<<dim3(Tn / 64, Cn / 64, Bn), 256>>>(c1b, x, nullptr);
    conv_kernel<2><<<dim3(Tn / 64, Cn / 64, Bn), 256>>>(c2b, x, out);
}

// round 15
// speedup vs baseline: 1.8475x; 1.0216x over previous
#include <cuda_runtime.h>
#include <cuda_bf16.h>
#include <mma.h>
#include <cstdint>

using namespace nvcuda;

#define Bn   16
#define Cn   256
#define Tn   1024
#define KEYn 256
#define INV_SQRT_K 0.0625f

// ---------------- scratch (device globals; no allocation allowed) ----------
__device__ __nv_bfloat16 g_q[Bn * KEYn * Tn];    // channel-major [B,KEY,T] bf16
__device__ __nv_bfloat16 g_k[Bn * KEYn * Tn];    // channel-major [B,KEY,T] bf16
__device__ float g_v[Bn * Tn * Cn];              // token-major   [B,T,C]
__device__ __nv_bfloat16 g_attn[(size_t)Bn * Tn * Tn]; // exp(scores), bf16
__device__ float g_colpart[(size_t)16 * Bn * Tn];
__device__ float g_invcol[Bn * Tn];
__device__ float g_rowsum[Bn * Tn];
__device__ float g_wx[Bn * Tn];
__device__ __nv_bfloat16 g_oa[Bn * Cn * Tn];     // attention out, bf16
__device__ __nv_bfloat16 g_h1[Bn * Cn * Tn];     // conv1 out, bf16
__device__ __nv_bfloat16 g_ws1[3 * Cn * Cn];     // weight-normed bf16, [r][c][o]
__device__ __nv_bfloat16 g_ws2[3 * Cn * Cn];

// ---------------- weight norm (both convs in one launch) -------------------
__global__ __launch_bounds__(256) void wnorm_kernel(const float* __restrict__ v1,
                                                    const float* __restrict__ g1,
                                                    const float* __restrict__ v2,
                                                    const float* __restrict__ g2) {
    int which = blockIdx.x >> 8;
    int o = blockIdx.x & 255;
    const float* v = which ? v2 : v1;
    const float* g = which ? g2 : g1;
    __nv_bfloat16* w = which ? g_ws2 : g_ws1;
    int tid = threadIdx.x;
    __shared__ float red[256];
    float s = 0.f;
    for (int i = tid; i < Cn * 3; i += 256) {
        float t = v[o * Cn * 3 + i];
        s += t * t;
    }
    red[tid] = s;
    __syncthreads();
    for (int st = 128; st > 0; st >>= 1) {
        if (tid < st) red[tid] += red[tid + st];
        __syncthreads();
    }
    float scale = g[o] * rsqrtf(red[0]);
    for (int i = tid; i < Cn * 3; i += 256) {
        int c = i / 3, r = i - c * 3;
        w[(r * Cn + c) * Cn + o] = __float2bfloat16(v[o * Cn * 3 + i] * scale);
    }
}

// ------- fused q/k/v projection (bf16 wmma 16x16x16, K-step 32) ------------
__global__ __launch_bounds__(256) void gemm_qkv_wmma(
        const float* __restrict__ x,
        const float* __restrict__ Wq, const float* __restrict__ bq,
        const float* __restrict__ Wk, const float* __restrict__ bk,
        const float* __restrict__ Wv, const float* __restrict__ bv) {
    int b = blockIdx.z;
    int t0 = blockIdx.x * 64;
    int by = blockIdx.y;
    int which = by >> 2;               // 0=q 1=k 2=v
    int n0 = (by & 3) * 64;
    const float* W = (which == 0) ? Wq : (which == 1) ? Wk : Wv;
    const float* bias = (which == 0) ? bq : (which == 1) ? bk : bv;
    int tid = threadIdx.x;
    __shared__ union {
        struct {
            alignas(16) __nv_bfloat16 W[32][72];
            alignas(16) __nv_bfloat16 X[32][72];
        } mi;
        float S[64][72];
    } sm;
    int wid = tid >> 5;
    int m_off = (wid & 3) * 16;        // n
    int n_base = (wid >> 2) * 32;      // t
    wmma::fragment<wmma::accumulator, 16, 16, 16, float> acc[2];
    wmma::fill_fragment(acc[0], 0.f);
    wmma::fill_fragment(acc[1], 0.f);
    const float* xb = x + (size_t)b * Cn * Tn;
    int lr = tid >> 4, lc = (tid & 15) * 4;
    for (int c0 = 0; c0 < Cn; c0 += 32) {
#pragma unroll
        for (int h = 0; h < 2; h++) {
            float4 wv = *(const float4*)&W[(c0 + lr + h * 16) * 256 + n0 + lc];
            *(__nv_bfloat162*)&sm.mi.W[lr + h * 16][lc] = __floats2bfloat162_rn(wv.x, wv.y);
            *(__nv_bfloat162*)&sm.mi.W[lr + h * 16][lc + 2] = __floats2bfloat162_rn(wv.z, wv.w);
            float4 xv = *(const float4*)&xb[(size_t)(c0 + lr + h * 16) * Tn + t0 + lc];
            *(__nv_bfloat162*)&sm.mi.X[lr + h * 16][lc] = __floats2bfloat162_rn(xv.x, xv.y);
            *(__nv_bfloat162*)&sm.mi.X[lr + h * 16][lc + 2] = __floats2bfloat162_rn(xv.z, xv.w);
        }
        __syncthreads();
#pragma unroll
        for (int ks = 0; ks < 32; ks += 16) {
            wmma::fragment<wmma::matrix_a, 16, 16, 16, __nv_bfloat16, wmma::col_major> a;
            wmma::load_matrix_sync(a, &sm.mi.W[ks][m_off], 72);
#pragma unroll
            for (int nf = 0; nf < 2; nf++) {
                wmma::fragment<wmma::matrix_b, 16, 16, 16, __nv_bfloat16, wmma::row_major> bf;
                wmma::load_matrix_sync(bf, &sm.mi.X[ks][n_base + nf * 16], 72);
                wmma::mma_sync(acc[nf], a, bf, acc[nf]);
            }
        }
        __syncthreads();
    }
    wmma::store_matrix_sync(&sm.S[m_off][n_base], acc[0], 72, wmma::mem_row_major);
    wmma::store_matrix_sync(&sm.S[m_off][n_base + 16], acc[1], 72, wmma::mem_row_major);
    __syncthreads();
    if (which < 2) {   // q/k: channel-major [n][t], bf16
        __nv_bfloat16* out = (which == 0) ? g_q : g_k;
        int row = tid >> 2, colb = (tid & 3) * 16;
        int n = n0 + row;
        float bo = bias[n];
        __nv_bfloat16* orow = &out[((size_t)b * KEYn + n) * Tn + t0 + colb];
#pragma unroll
        for (int q = 0; q < 4; q++) {
            *(__nv_bfloat162*)&orow[q * 4] = __floats2bfloat162_rn(
                sm.S[row][colb + q * 4 + 0] + bo, sm.S[row][colb + q * 4 + 1] + bo);
            *(__nv_bfloat162*)&orow[q * 4 + 2] = __floats2bfloat162_rn(
                sm.S[row][colb + q * 4 + 2] + bo, sm.S[row][colb + q * 4 + 3] + bo);
        }
    } else {           // v: token-major [t][c], fp32, transposed write via smem
        int col = tid >> 2;            // t index 0..63
        int rowb = (tid & 3) * 16;     // n chunk
#pragma unroll
        for (int q = 0; q < 4; q++) {
            float4 res;
            res.x = sm.S[rowb + q * 4 + 0][col] + bias[n0 + rowb + q * 4 + 0];
            res.y = sm.S[rowb + q * 4 + 1][col] + bias[n0 + rowb + q * 4 + 1];
            res.z = sm.S[rowb + q * 4 + 2][col] + bias[n0 + rowb + q * 4 + 2];
            res.w = sm.S[rowb + q * 4 + 3][col] + bias[n0 + rowb + q * 4 + 3];
            *(float4*)&g_v[((size_t)b * Tn + t0 + col) * Cn + n0 + rowb + q * 4] = res;
        }
    }
}

// ------- scores (bf16 wmma 16x16x16, triangular grid, K-step 32) -----------
__global__ __launch_bounds__(256) void gemm_scores() {
    int b = blockIdx.z;
    int idx = blockIdx.x;
    int jt = (int)((sqrtf(8.f * idx + 1.f) - 1.f) * 0.5f);
    while ((jt + 1) * (jt + 2) / 2 <= idx) jt++;
    while (jt * (jt + 1) / 2 > idx) jt--;
    int it = idx - jt * (jt + 1) / 2;
    int i0 = it * 64, j0 = jt * 64;
    int tid = threadIdx.x;
    __nv_bfloat16* S = g_attn + (size_t)b * Tn * Tn;
    float* cpart = g_colpart + (size_t)jt * Bn * Tn + b * Tn + i0;
    int c = tid & 63, rb = tid >> 6;
    __shared__ union {
        struct {
            alignas(16) __nv_bfloat16 Q[32][72];
            alignas(16) __nv_bfloat16 K[32][72];
        } mi;
        struct { float S[64][72]; float cred[4][64]; } ep;
    } sm;
    int wid = tid >> 5;
    int m_off = (wid & 3) * 16;
    int n_base = (wid >> 2) * 32;
    const __nv_bfloat16* qb = g_q + (size_t)b * KEYn * Tn;
    const __nv_bfloat16* kb = g_k + (size_t)b * KEYn * Tn;
    wmma::fragment<wmma::accumulator, 16, 16, 16, float> acc[2];
    wmma::fill_fragment(acc[0], 0.f);
    wmma::fill_fragment(acc[1], 0.f);
    int lr = tid >> 3, lc = (tid & 7) * 8;   // 32 rows x 64 bf16 per tile fill
    for (int kc = 0; kc < KEYn; kc += 32) {
        *(float4*)&sm.mi.Q[lr][lc] = *(const float4*)&qb[(size_t)(kc + lr) * Tn + j0 + lc];
        *(float4*)&sm.mi.K[lr][lc] = *(const float4*)&kb[(size_t)(kc + lr) * Tn + i0 + lc];
        __syncthreads();
#pragma unroll
        for (int ks = 0; ks < 32; ks += 16) {
            wmma::fragment<wmma::matrix_a, 16, 16, 16, __nv_bfloat16, wmma::col_major> a;
            wmma::load_matrix_sync(a, &sm.mi.Q[ks][m_off], 72);
#pragma unroll
            for (int nf = 0; nf < 2; nf++) {
                wmma::fragment<wmma::matrix_b, 16, 16, 16, __nv_bfloat16, wmma::row_major> bf;
                wmma::load_matrix_sync(bf, &sm.mi.K[ks][n_base + nf * 16], 72);
                wmma::mma_sync(acc[nf], a, bf, acc[nf]);
            }
        }
        __syncthreads();
    }
    wmma::store_matrix_sync(&sm.ep.S[m_off][n_base], acc[0], 72, wmma::mem_row_major);
    wmma::store_matrix_sync(&sm.ep.S[m_off][n_base + 16], acc[1], 72, wmma::mem_row_major);
    __syncthreads();
    float csum = 0.f;
#pragma unroll
    for (int rr = 0; rr < 16; rr++) {
        int row = rb * 16 + rr;
        int j = j0 + row, i = i0 + c;
        float e = (i <= j) ? __expf(sm.ep.S[row][c] * INV_SQRT_K) : 0.f;
        S[(size_t)j * Tn + i] = __float2bfloat16(e);
        csum += e;
    }
    sm.ep.cred[rb][c] = csum;
    __syncthreads();
    if (tid < 64) {
        float s = sm.ep.cred[0][tid] + sm.ep.cred[1][tid]
                + sm.ep.cred[2][tid] + sm.ep.cred[3][tid];
        cpart[tid] = s;
    }
}

// ------- invcol[b,i] = 1 / sum_{p >= i_tile} colpart[p][b,i] ---------------
__global__ __launch_bounds__(256) void invcol_kernel() {
    int idx = blockIdx.x * 256 + threadIdx.x;
    int i = idx & (Tn - 1);
    int p0 = i >> 6;
    float s = 0.f;
    for (int p = p0; p < 16; p++) s += g_colpart[(size_t)p * Bn * Tn + idx];
    g_invcol[idx] = 1.f / s;
}

// ------- rowsum[b,j] = sum_{i<=j} e[b,j,i] * invcol[b,i]  (vectorized) -----
__global__ __launch_bounds__(256) void row_sum() {
    int b = blockIdx.y;
    int j = blockIdx.x * 8 + (threadIdx.x >> 5);
    int lane = threadIdx.x & 31;
    const __nv_bfloat16* row = g_attn + (size_t)b * Tn * Tn + (size_t)j * Tn;
    const float* inv = g_invcol + b * Tn;
    float s = 0.f;
    for (int i8 = lane * 8; i8 <= j; i8 += 256) {
        float4 raw = *(const float4*)&row[i8];
        const __nv_bfloat16* e8 = (const __nv_bfloat16*)&raw;
#pragma unroll
        for (int t = 0; t < 8; t++) {
            int i = i8 + t;
            if (i <= j) s += __bfloat162float(e8[t]) * inv[i];
        }
    }
#pragma unroll
    for (int o = 16; o > 0; o >>= 1) s += __shfl_xor_sync(0xffffffffu, s, o);
    if (lane == 0) g_rowsum[b * Tn + j] = s;
}

// ------- weight_x[b,:] = softmax_j(rowsum[b,:]) ----------------------------
__global__ __launch_bounds__(256) void wx_softmax() {
    int b = blockIdx.x;
    int tid = threadIdx.x;
    __shared__ float red[256];
    const float* r = g_rowsum + b * Tn;
    float m = -1e30f;
    for (int j = tid; j < Tn; j += 256) m = fmaxf(m, r[j]);
    red[tid] = m;
    __syncthreads();
    for (int st = 128; st > 0; st >>= 1) {
        if (tid < st) red[tid] = fmaxf(red[tid], red[tid + st]);
        __syncthreads();
    }
    m = red[0];
    __syncthreads();
    float sum = 0.f;
    for (int j = tid; j < Tn; j += 256) sum += __expf(r[j] - m);
    red[tid] = sum;
    __syncthreads();
    for (int st = 128; st > 0; st >>= 1) {
        if (tid < st) red[tid] += red[tid + st];
        __syncthreads();
    }
    float inv = 1.f / red[0];
    for (int j = tid; j < Tn; j += 256)
        g_wx[b * Tn + j] = __expf(r[j] - m) * inv;
}

// ------- attn·V (bf16 wmma 16x16x16, K-step 32, union smem) ----------------
__global__ __launch_bounds__(256) void gemm_av() {
    int b = blockIdx.z;
    int j0 = blockIdx.x * 64, c0 = blockIdx.y * 64;
    int tid = threadIdx.x;
    __shared__ union {
        struct {
            alignas(16) __nv_bfloat16 As[32][72];  // [i][c] scaled v
            alignas(16) __nv_bfloat16 Es[64][40];  // [j][i-chunk 32 + pad]
        } mi;
        float S[64][72];
    } sm;
    const __nv_bfloat16* A = g_attn + (size_t)b * Tn * Tn;
    const float* V = g_v + (size_t)b * Tn * Cn;
    const float* inv = g_invcol + b * Tn;
    int wid = tid >> 5;
    int m_off = (wid & 3) * 16;          // c
    int n_base = (wid >> 2) * 32;        // j
    wmma::fragment<wmma::accumulator, 16, 16, 16, float> acc[2];
    wmma::fill_fragment(acc[0], 0.f);
    wmma::fill_fragment(acc[1], 0.f);
    int ar = tid >> 4, ac = (tid & 15) * 4;
    int er = tid >> 2, ec = (tid & 3) * 8;
    int kend = j0 + 64;
    for (int ii = 0; ii < kend; ii += 32) {
#pragma unroll
        for (int h = 0; h < 2; h++) {
            int irow = ii + ar + h * 16;
            float sc = inv[irow];
            float4 v4 = *(const float4*)&V[(size_t)irow * Cn + c0 + ac];
            *(__nv_bfloat162*)&sm.mi.As[ar + h * 16][ac] =
                __floats2bfloat162_rn(v4.x * sc, v4.y * sc);
            *(__nv_bfloat162*)&sm.mi.As[ar + h * 16][ac + 2] =
                __floats2bfloat162_rn(v4.z * sc, v4.w * sc);
        }
        // 8 bf16 (16 bytes) direct copy from bf16 attn
        *(float4*)&sm.mi.Es[er][ec] = *(const float4*)&A[(size_t)(j0 + er) * Tn + ii + ec];
        __syncthreads();
#pragma unroll
        for (int ks = 0; ks < 32; ks += 16) {
            wmma::fragment<wmma::matrix_a, 16, 16, 16, __nv_bfloat16, wmma::col_major> a;
            wmma::load_matrix_sync(a, &sm.mi.As[ks][m_off], 72);
#pragma unroll
            for (int nf = 0; nf < 2; nf++) {
                wmma::fragment<wmma::matrix_b, 16, 16, 16, __nv_bfloat16, wmma::col_major> bf;
                wmma::load_matrix_sync(bf, &sm.mi.Es[n_base + nf * 16][ks], 40);
                wmma::mma_sync(acc[nf], a, bf, acc[nf]);
            }
        }
        __syncthreads();
    }
    wmma::store_matrix_sync(&sm.S[m_off][n_base], acc[0], 72, wmma::mem_row_major);
    wmma::store_matrix_sync(&sm.S[m_off][n_base + 16], acc[1], 72, wmma::mem_row_major);
    __syncthreads();
    int row = tid >> 2, colb = (tid & 3) * 16;
    __nv_bfloat16* orow = &g_oa[((size_t)b * Cn + c0 + row) * Tn + j0 + colb];
#pragma unroll
    for (int q = 0; q < 4; q++) {
        *(__nv_bfloat162*)&orow[q * 4] = __floats2bfloat162_rn(
            sm.S[row][colb + q * 4 + 0], sm.S[row][colb + q * 4 + 1]);
        *(__nv_bfloat162*)&orow[q * 4 + 2] = __floats2bfloat162_rn(
            sm.S[row][colb + q * 4 + 2], sm.S[row][colb + q * 4 + 3]);
    }
}

// ------- causal conv (bf16 wmma 16x16x16 implicit GEMM, KS=3) + fusion -----
template <int WHICH>
__global__ __launch_bounds__(256) void conv_kernel(const float* __restrict__ bias,
                                                   const float* __restrict__ x,
                                                   float* __restrict__ out_final) {
    const __nv_bfloat16* in = (WHICH == 1) ? g_oa : g_h1;
    const __nv_bfloat16* w = (WHICH == 1) ? g_ws1 : g_ws2;
    int b = blockIdx.z;
    int t0 = blockIdx.x * 64, o0 = blockIdx.y * 64;
    int tid = threadIdx.x;
    __shared__ alignas(16) __nv_bfloat16 As[3][16][72];   // [r][c][o]
    __shared__ alignas(16) __nv_bfloat16 In3[3][16][72];  // [r][c][t per tap]
    __shared__ float Ss[64][72];
    int wid = tid >> 5;
    int m_off = (wid & 3) * 16;       // o
    int n_base = (wid >> 2) * 32;     // t
    wmma::fragment<wmma::accumulator, 16, 16, 16, float> acc[2];
    wmma::fill_fragment(acc[0], 0.f);
    wmma::fill_fragment(acc[1], 0.f);
    const __nv_bfloat16* inb = in + (size_t)b * Cn * Tn;
    const __nv_bfloat16 zero_bf = __float2bfloat16(0.f);
    for (int cc0 = 0; cc0 < Cn; cc0 += 16) {
#pragma unroll
        for (int q = 0; q < 3; q++) {
            int lin = tid + q * 256;          // 0..767
            int row = lin >> 4;               // 0..47
            int r = row >> 4, kk = row & 15;
            int col = (lin & 15) * 4;
            *(float2*)&As[r][kk][col] =
                *(const float2*)&w[((r * Cn) + cc0 + kk) * Cn + o0 + col];
        }
#pragma unroll
        for (int q = 0; q < 12; q++) {
            int lin = tid + q * 256;          // 0..3071
            int r = lin >> 10;
            int rem = lin & 1023;
            int kk = rem >> 6, col = rem & 63;
            int gt = t0 + col - 2 + r;
            In3[r][kk][col] = (gt >= 0)
                ? inb[(size_t)(cc0 + kk) * Tn + gt] : zero_bf;
        }
        __syncthreads();
#pragma unroll
        for (int r = 0; r < 3; r++) {
            wmma::fragment<wmma::matrix_a, 16, 16, 16, __nv_bfloat16, wmma::col_major> a;
            wmma::load_matrix_sync(a, &As[r][0][m_off], 72);
#pragma unroll
            for (int nf = 0; nf < 2; nf++) {
                wmma::fragment<wmma::matrix_b, 16, 16, 16, __nv_bfloat16, wmma::row_major> bf;
                wmma::load_matrix_sync(bf, &In3[r][0][n_base + nf * 16], 72);
                wmma::mma_sync(acc[nf], a, bf, acc[nf]);
            }
        }
        __syncthreads();
    }
    wmma::store_matrix_sync(&Ss[m_off][n_base], acc[0], 72, wmma::mem_row_major);
    wmma::store_matrix_sync(&Ss[m_off][n_base + 16], acc[1], 72, wmma::mem_row_major);
    __syncthreads();
    int row = tid >> 2, colb = (tid & 3) * 16;
    int o = o0 + row;
    float bo = bias[o];
    if (WHICH == 2) {
        const float* xrow = &x[((size_t)b * Cn + o) * Tn + t0 + colb];
        const float* wxp = &g_wx[b * Tn + t0 + colb];
        float* orow = &out_final[((size_t)b * Cn + o) * Tn + t0 + colb];
#pragma unroll
        for (int q = 0; q < 4; q++) {
            float4 xv = *(const float4*)&xrow[q * 4];
            float4 wx4 = *(const float4*)&wxp[q * 4];
            float4 res;
            float h0 = fmaxf(Ss[row][colb + q * 4 + 0] + bo, 0.f);
            float h1 = fmaxf(Ss[row][colb + q * 4 + 1] + bo, 0.f);
            float h2 = fmaxf(Ss[row][colb + q * 4 + 2] + bo, 0.f);
            float h3 = fmaxf(Ss[row][colb + q * 4 + 3] + bo, 0.f);
            res.x = fmaxf(h0 + xv.x + wx4.x * xv.x, 0.f);
            res.y = fmaxf(h1 + xv.y + wx4.y * xv.y, 0.f);
            res.z = fmaxf(h2 + xv.z + wx4.z * xv.z, 0.f);
            res.w = fmaxf(h3 + xv.w + wx4.w * xv.w, 0.f);
            *(float4*)&orow[q * 4] = res;
        }
    } else {
        __nv_bfloat16* orow = &g_h1[((size_t)b * Cn + o) * Tn + t0 + colb];
#pragma unroll
        for (int q = 0; q < 4; q++) {
            *(__nv_bfloat162*)&orow[q * 4] = __floats2bfloat162_rn(
                fmaxf(Ss[row][colb + q * 4 + 0] + bo, 0.f),
                fmaxf(Ss[row][colb + q * 4 + 1] + bo, 0.f));
            *(__nv_bfloat162*)&orow[q * 4 + 2] = __floats2bfloat162_rn(
                fmaxf(Ss[row][colb + q * 4 + 2] + bo, 0.f),
                fmaxf(Ss[row][colb + q * 4 + 3] + bo, 0.f));
        }
    }
}

// ---------------------------------------------------------------------------
extern "C" void kernel_launch(void* const* d_in, const int* in_sizes, int n_in,
                              void* d_out, int out_size) {
    const float* x   = (const float*)d_in[0];
    const float* Wq  = (const float*)d_in[1];
    const float* bq  = (const float*)d_in[2];
    const float* Wk  = (const float*)d_in[3];
    const float* bk  = (const float*)d_in[4];
    const float* Wv  = (const float*)d_in[5];
    const float* bv  = (const float*)d_in[6];
    const float* c1v = (const float*)d_in[7];
    const float* c1g = (const float*)d_in[8];
    const float* c1b = (const float*)d_in[9];
    const float* c2v = (const float*)d_in[10];
    const float* c2g = (const float*)d_in[11];
    const float* c2b = (const float*)d_in[12];
    float* out = (float*)d_out;

    wnorm_kernel<<<2 * Cn, 256>>>(c1v, c1g, c2v, c2g);

    gemm_qkv_wmma<<<dim3(Tn / 64, 12, Bn), 256>>>(x, Wq, bq, Wk, bk, Wv, bv);

    gemm_scores<<<dim3(136, 1, Bn), 256>>>();   // triangular tile grid
    invcol_kernel<<<(Bn * Tn) / 256, 256>>>();
    row_sum<<<dim3(Tn / 8, Bn), 256>>>();
    wx_softmax<<<Bn, 256>>>();
    gemm_av<<<dim3(Tn / 64, Cn / 64, Bn), 256>>>();

    conv_kernel<1><<<dim3(Tn / 64, Cn / 64, Bn), 256>>>(c1b, x, nullptr);
    conv_kernel<2><<<dim3(Tn / 64, Cn / 64, Bn), 256>>>(c2b, x, out);
}